// round 6
// baseline (speedup 1.0000x reference)
#include <cuda_runtime.h>
#include <cuda_bf16.h>
#include <mma.h>
#include <cstdint>
using namespace nvcuda;
typedef __nv_bfloat16 bf16;

#define Bv 1024
#define Hv 512
#define TIN 336
#define TOUT 168
#define KB0 1600
#define KB1 3072
#define KBF 1536
#define NCTA 128
#define NTHR 256
#define LDK 40
#define ROWB 144
#define TILE_B (128*ROWB)
#define STG_B (2*TILE_B)
#define DSM (1024 + 4*STG_B)

__device__ __align__(128) bf16 g_We0[(size_t)2048*KB0];
__device__ __align__(128) bf16 g_We1[(size_t)2048*KB1];
__device__ __align__(128) bf16 g_Wd0[(size_t)2048*KB0];
__device__ __align__(128) bf16 g_Wd1[(size_t)2048*KB1];
__device__ __align__(128) bf16 g_Wf1[(size_t)256*KBF];
__device__ __align__(128) bf16 g_A0[(size_t)2*Bv*KB0];
__device__ __align__(128) bf16 g_A1[(size_t)2*Bv*KB1];
__device__ __align__(128) bf16 g_xb[(size_t)Bv*TIN*48];
__device__ __align__(128) float g_c0[Bv*Hv];
__device__ __align__(128) float g_c1[Bv*Hv];
__device__ __align__(128) float g_hid[Bv*256];
__device__ unsigned g_cnt = 0;
__device__ volatile unsigned g_gen = 0;

__device__ __forceinline__ void cpa16(void* s, const void* g) {
    unsigned a = (unsigned)__cvta_generic_to_shared(s);
    asm volatile("cp.async.cg.shared.global [%0], [%1], 16;" :: "r"(a), "l"(g));
}
__device__ __forceinline__ void cpcommit() { asm volatile("cp.async.commit_group;"); }
__device__ __forceinline__ void cpwait0()  { asm volatile("cp.async.wait_group 0;"); }
__device__ __forceinline__ void cpwait1()  { asm volatile("cp.async.wait_group 1;"); }
__device__ __forceinline__ float sigf(float x) { return 1.f / (1.f + __expf(-x)); }

__device__ __forceinline__ void gbar() {
    __syncthreads();
    __threadfence();
    if (threadIdx.x == 0) {
        unsigned gen = g_gen;
        if (atomicAdd(&g_cnt, 1u) == (unsigned)(gridDim.x - 1)) {
            g_cnt = 0; __threadfence(); g_gen = gen + 1;
        } else {
            while (g_gen == gen) { __nanosleep(64); }
        }
        __threadfence();
    }
    __syncthreads();
}
__device__ __forceinline__ void mbar_wait(uint32_t mbar, uint32_t parity) {
    uint32_t done = 0;
    while (!done) {
        asm volatile("{\n\t.reg .pred p;\n\t"
            "mbarrier.try_wait.parity.acquire.cta.shared::cta.b64 p, [%1], %2;\n\t"
            "selp.b32 %0,1,0,p;\n\t}" : "=r"(done) : "r"(mbar), "r"(parity) : "memory");
    }
}
__device__ __forceinline__ void ldsm4(uint32_t& r0, uint32_t& r1, uint32_t& r2, uint32_t& r3, uint32_t a) {
    asm volatile("ldmatrix.sync.aligned.m8n8.x4.shared.b16 {%0,%1,%2,%3}, [%4];"
        : "=r"(r0), "=r"(r1), "=r"(r2), "=r"(r3) : "r"(a));
}
__device__ __forceinline__ void hmma(float* c, uint32_t a0, uint32_t a1, uint32_t a2, uint32_t a3,
                                     uint32_t b0, uint32_t b1) {
    asm volatile("mma.sync.aligned.m16n8k16.row.col.f32.bf16.bf16.f32 "
        "{%0,%1,%2,%3}, {%4,%5,%6,%7}, {%8,%9}, {%0,%1,%2,%3};"
        : "+f"(c[0]), "+f"(c[1]), "+f"(c[2]), "+f"(c[3])
        : "r"(a0), "r"(a1), "r"(a2), "r"(a3), "r"(b0), "r"(b1));
}

// cell: C[128b x 128(u*4+gate)] = A @ W'^T, register-resident LSTM epilogue
__device__ void cell_tc(char* dyn, unsigned& pb,
    const bf16* Ag, const bf16* Wg, int KB, const float* bias, float* cst,
    bf16* h0d, int h0stride, int h0off, bf16* h1d,
    bf16* xdst, const bf16* xsrc, int xt)
{
    const int tid = threadIdx.x, cta = blockIdx.x;
    const int b0 = (cta >> 4) * 128;
    const int u0 = (cta & 15) * 32;
    const int w0 = (cta & 15) * 128;
    const int nCh = KB >> 6;
    uint32_t sm0 = (uint32_t)__cvta_generic_to_shared(dyn);

    auto issue = [&](int kc) {
        int st = kc & 3;
        uint32_t mb = sm0 + st * 8;
        if (tid == 0)
            asm volatile("mbarrier.arrive.expect_tx.shared.b64 _, [%0], %1;"
                         :: "r"(mb), "r"(32768u) : "memory");
        int row = tid & 127;
        const bf16* src = (tid < 128)
            ? (Ag + (size_t)(b0 + row) * KB + kc * 64)
            : (Wg + (size_t)(w0 + row) * KB + kc * 64);
        uint32_t dst = sm0 + 1024 + st * STG_B + ((tid < 128) ? 0 : TILE_B) + row * ROWB;
        asm volatile("cp.async.bulk.shared::cluster.global.mbarrier::complete_tx::bytes [%0], [%1], %2, [%3];"
                     :: "r"(dst), "l"(src), "r"(128u), "r"(mb) : "memory");
    };

    const int lane = tid & 31, warp = tid >> 5;
    const int mi = warp >> 2, nj = warp & 3;
    float acc[4][4][4];
    #pragma unroll
    for (int i = 0; i < 4; i++)
        #pragma unroll
        for (int j = 0; j < 4; j++)
            #pragma unroll
            for (int k = 0; k < 4; k++) acc[i][j][k] = 0.f;

    for (int k = 0; k < 4; k++) issue(k);

    for (int kc = 0; kc < nCh; kc++) {
        int st = kc & 3;
        mbar_wait(sm0 + st * 8, (pb >> st) & 1);
        pb ^= (1u << st);
        uint32_t Ab = sm0 + 1024 + st * STG_B;
        uint32_t arow  = Ab + (mi * 64 + (lane & 15)) * ROWB + ((lane >> 4) << 4);
        uint32_t brow0 = Ab + TILE_B + (nj * 32 + (lane & 15)) * ROWB + ((lane >> 4) << 4);
        #pragma unroll
        for (int k16 = 0; k16 < 4; k16++) {
            uint32_t kb = k16 * 32;
            uint32_t a[4][4], q0[4], q1[4];
            #pragma unroll
            for (int im = 0; im < 4; im++)
                ldsm4(a[im][0], a[im][1], a[im][2], a[im][3], arow + im * (16 * ROWB) + kb);
            ldsm4(q0[0], q0[1], q0[2], q0[3], brow0 + kb);
            ldsm4(q1[0], q1[1], q1[2], q1[3], brow0 + 16 * ROWB + kb);
            #pragma unroll
            for (int im = 0; im < 4; im++) {
                hmma(acc[im][0], a[im][0], a[im][1], a[im][2], a[im][3], q0[0], q0[2]);
                hmma(acc[im][1], a[im][0], a[im][1], a[im][2], a[im][3], q0[1], q0[3]);
                hmma(acc[im][2], a[im][0], a[im][1], a[im][2], a[im][3], q1[0], q1[2]);
                hmma(acc[im][3], a[im][0], a[im][1], a[im][2], a[im][3], q1[1], q1[3]);
            }
        }
        __syncthreads();
        if (kc + 4 < nCh) issue(kc + 4);
    }

    const int q = lane & 3, r = lane >> 2;
    #pragma unroll
    for (int im = 0; im < 4; im++)
        #pragma unroll
        for (int jn = 0; jn < 4; jn++) {
            float* c4 = acc[im][jn];
            float x0 = __shfl_xor_sync(0xffffffffu, c4[0], 1);
            float x1 = __shfl_xor_sync(0xffffffffu, c4[1], 1);
            float x2 = __shfl_xor_sync(0xffffffffu, c4[2], 1);
            float x3 = __shfl_xor_sync(0xffffffffu, c4[3], 1);
            int u = u0 + nj * 8 + jn * 2 + (q >> 1);
            int row; float gi, gf, gg, go;
            if ((q & 1) == 0) { row = mi * 64 + im * 16 + r;     gi = c4[0]; gf = c4[1]; gg = x0;   go = x1; }
            else              { row = mi * 64 + im * 16 + r + 8; gi = x2;    gf = x3;    gg = c4[2]; go = c4[3]; }
            int b = b0 + row;
            gi += __ldg(bias + u);
            gf += __ldg(bias + 512 + u);
            gg += __ldg(bias + 1024 + u);
            go += __ldg(bias + 1536 + u);
            float co = cst[(size_t)u * Bv + b];
            float cn = sigf(gf) * co + sigf(gi) * tanhf(gg);
            float h  = sigf(go) * tanhf(cn);
            cst[(size_t)u * Bv + b] = cn;
            bf16 hi = __float2bfloat16(h);
            bf16 lo = __float2bfloat16(h - __bfloat162float(hi));
            bf16* d0 = h0d + (size_t)b * h0stride + h0off + 3 * u;
            d0[0] = hi; d0[1] = lo; d0[2] = hi;
            if (h1d) { bf16* d1 = h1d + (size_t)b * KB1 + 3 * u; d1[0] = hi; d1[1] = lo; d1[2] = hi; }
        }

    if (xdst && (cta & 15) == 0) {   // fill x-cols (0..47) of next A0 buffer
        for (int i = tid; i < 128 * 6; i += NTHR) {
            int row = i / 6, seg = i % 6;
            uint4* d = (uint4*)((char*)(xdst + (size_t)(b0 + row) * KB0) + seg * 16);
            if (xsrc) {
                *d = *(const uint4*)((const char*)(xsrc + ((size_t)(b0 + row) * TIN + xt) * 48) + seg * 16);
            } else *d = make_uint4(0, 0, 0, 0);
        }
    }
    __syncthreads();
}

__device__ void fc_phase(bf16* sm, const float* fb1, const bf16* A1rd)
{
    const int tid = threadIdx.x, cta = blockIdx.x;
    if (cta >= 64) return;
    const int b0 = (cta >> 3) * 128, n0 = (cta & 7) * 32;
    const int nCh = KBF / 32;
    auto load_chunk = [&](int kc, int bi) {
        bf16* As = sm + bi * (160 * LDK);
        bf16* Bs = As + 128 * LDK;
        const int kb = kc * 32;
        for (int s = tid; s < 640; s += NTHR) {
            int seg = s & 3;
            if (s < 512) {
                int row = s >> 2;
                cpa16(As + row * LDK + seg * 8, A1rd + (size_t)(b0 + row) * KB1 + 1536 + kb + seg * 8);
            } else {
                int row = (s - 512) >> 2;
                cpa16(Bs + row * LDK + seg * 8, g_Wf1 + (size_t)(n0 + row) * KBF + kb + seg * 8);
            }
        }
        cpcommit();
    };
    wmma::fragment<wmma::accumulator, 16, 16, 16, float> acc[2];
    wmma::fill_fragment(acc[0], 0.f);
    wmma::fill_fragment(acc[1], 0.f);
    const int warp = tid >> 5;
    load_chunk(0, 0);
    int bi = 0;
    for (int kc = 0; kc < nCh; kc++) {
        if (kc + 1 < nCh) { load_chunk(kc + 1, bi ^ 1); cpwait1(); }
        else cpwait0();
        __syncthreads();
        const bf16* As = sm + bi * (160 * LDK);
        const bf16* pa = As + warp * 16 * LDK;
        const bf16* pb = As + 128 * LDK;
        #pragma unroll
        for (int kk = 0; kk < 32; kk += 16) {
            wmma::fragment<wmma::matrix_a, 16, 16, 16, bf16, wmma::row_major> af;
            wmma::fragment<wmma::matrix_b, 16, 16, 16, bf16, wmma::col_major> bfr[2];
            wmma::load_matrix_sync(af, pa + kk, LDK);
            wmma::load_matrix_sync(bfr[0], pb + kk, LDK);
            wmma::load_matrix_sync(bfr[1], pb + 16 * LDK + kk, LDK);
            wmma::mma_sync(acc[0], af, bfr[0], acc[0]);
            wmma::mma_sync(acc[1], af, bfr[1], acc[1]);
        }
        __syncthreads();
        bi ^= 1;
    }
    float* Cs = (float*)sm;
    wmma::store_matrix_sync(Cs + warp * 16 * 36, acc[0], 36, wmma::mem_row_major);
    wmma::store_matrix_sync(Cs + warp * 16 * 36 + 16, acc[1], 36, wmma::mem_row_major);
    __syncthreads();
    for (int idx = tid; idx < 128 * 32; idx += NTHR) {
        int r = idx >> 5, cc = idx & 31;
        g_hid[(b0 + r) * 256 + n0 + cc] = fmaxf(Cs[r * 36 + cc] + __ldg(fb1 + n0 + cc), 0.f);
    }
    __syncthreads();
}

__device__ void pred_phase(int t, float* out, const float* w2, const float* b2, bf16* A0wr)
{
    int b = blockIdx.x * 8 + (threadIdx.x >> 5);
    int lane = threadIdx.x & 31;
    float s = 0.f;
    #pragma unroll 8
    for (int j = lane; j < 256; j += 32)
        s += __ldcg(&g_hid[b * 256 + j]) * __ldg(w2 + j);
    #pragma unroll
    for (int o = 16; o; o >>= 1) s += __shfl_down_sync(0xffffffffu, s, o);
    if (lane == 0) {
        float p = fmaxf(s + __ldg(b2), 0.f);
        out[b * TOUT + t] = p;
        bf16 hi = __float2bfloat16(p);
        bf16 lo = __float2bfloat16(p - __bfloat162float(hi));
        bf16* d = A0wr + (size_t)b * KB0;
        d[0] = hi; d[1] = lo; d[2] = hi;
    }
}

extern __shared__ __align__(1024) char dynsm[];
__global__ void __launch_bounds__(NTHR) lstm_main(
    const float* eb0, const float* eb1, const float* db0, const float* db1,
    const float* fb1, const float* fW2, const float* fb2, float* out)
{
    const int tid = threadIdx.x;
    uint32_t sm0 = (uint32_t)__cvta_generic_to_shared(dynsm);
    if (tid == 0) {
        #pragma unroll
        for (int s = 0; s < 4; s++)
            asm volatile("mbarrier.init.shared.b64 [%0], %1;" :: "r"(sm0 + s * 8), "r"(1u) : "memory");
    }
    __syncthreads();
    unsigned pb = 0;
    bf16* fcsm = (bf16*)(dynsm + 1024);
    const size_t A0SZ = (size_t)Bv * KB0, A1SZ = (size_t)Bv * KB1;

    for (int s = 0; s < TIN; s++) {
        int p = s & 1;
        cell_tc(dynsm, pb, g_A0 + p * A0SZ, g_We0, KB0, eb0, g_c0,
                g_A0 + (p ^ 1) * A0SZ, KB0, 48, g_A1 + (p ^ 1) * A1SZ,
                g_A0 + (p ^ 1) * A0SZ, (s + 1 < TIN) ? g_xb : nullptr, s + 1);
        gbar();
        cell_tc(dynsm, pb, g_A1 + (p ^ 1) * A1SZ, g_We1, KB1, eb1, g_c1,
                g_A1 + p * A1SZ, KB1, 1536, nullptr, nullptr, nullptr, 0);
        gbar();
    }
    for (int td = 0; td < TOUT; td++) {
        int p = (TIN + td) & 1;
        cell_tc(dynsm, pb, g_A0 + p * A0SZ, g_Wd0, KB0, db0, g_c0,
                g_A0 + (p ^ 1) * A0SZ, KB0, 48, g_A1 + (p ^ 1) * A1SZ,
                g_A0 + (p ^ 1) * A0SZ, nullptr, 0);
        gbar();
        cell_tc(dynsm, pb, g_A1 + (p ^ 1) * A1SZ, g_Wd1, KB1, db1, g_c1,
                g_A1 + p * A1SZ, KB1, 1536, nullptr, nullptr, nullptr, 0);
        gbar();
        fc_phase(fcsm, fb1, g_A1 + p * A1SZ);
        gbar();
        pred_phase(td, out, fW2, fb2, g_A0 + (p ^ 1) * A0SZ);
        gbar();
    }
}

// prep: weights triple-split; cell weights row-interleaved (r' = 4u+gate)
__global__ void prep_w(const float* Wih, const float* Whh, int which,
                       int Fin, int Fpad, int Kf, int KB, int rows, int ileave)
{
    bf16* dst = (which == 0) ? g_We0 : (which == 1) ? g_We1 :
                (which == 2) ? g_Wd0 : (which == 3) ? g_Wd1 : g_Wf1;
    size_t tot = (size_t)rows * KB;
    size_t stride = (size_t)gridDim.x * blockDim.x;
    for (size_t e = (size_t)blockIdx.x * blockDim.x + threadIdx.x; e < tot; e += stride) {
        int col = (int)(e % KB);
        int rp = (int)(e / KB);
        int g = ileave ? ((rp & 3) * 512 + (rp >> 2)) : rp;
        float v = 0.f;
        int inrange = (col < 3 * Kf);
        int k = col / 3, slot = col - 3 * k;
        if (inrange) {
            if (k < Fin)       v = Wih[(size_t)g * Fin + k];
            else if (k < Fpad) v = 0.f;
            else               v = Whh[(size_t)g * Hv + (k - Fpad)];
        }
        bf16 hi = __float2bfloat16(v);
        bf16 lo = __float2bfloat16(v - __bfloat162float(hi));
        dst[e] = (!inrange) ? __float2bfloat16(0.f) : ((slot == 2) ? lo : hi);
    }
}

__global__ void prep_x(const float* x)
{
    size_t tot = (size_t)Bv * TIN * 48;
    size_t stride = (size_t)gridDim.x * blockDim.x;
    for (size_t e = (size_t)blockIdx.x * blockDim.x + threadIdx.x; e < tot; e += stride) {
        int col = (int)(e % 48);
        size_t row = e / 48;
        int k = col / 3, slot = col - 3 * k;
        float v = x[row * 16 + k];
        bf16 hi = __float2bfloat16(v);
        bf16 lo = __float2bfloat16(v - __bfloat162float(hi));
        g_xb[e] = (slot == 1) ? lo : hi;
    }
}

__global__ void prep_zero(const float* x)
{
    size_t stride = (size_t)gridDim.x * blockDim.x;
    size_t i0 = (size_t)blockIdx.x * blockDim.x + threadIdx.x;
    bf16 z = __float2bfloat16(0.f);
    for (size_t e = i0; e < (size_t)2 * Bv * KB0; e += stride) {
        size_t p = e / ((size_t)Bv * KB0);
        size_t rem = e - p * (size_t)Bv * KB0;
        int col = (int)(rem % KB0);
        bf16 v = z;
        if (p == 0 && col < 48) {       // x_0 triple for step 0, buffer 0
            int b = (int)(rem / KB0);
            int k = col / 3, slot = col - 3 * k;
            float xv = x[(size_t)b * (TIN * 16) + k];
            bf16 hi = __float2bfloat16(xv);
            v = (slot == 1) ? __float2bfloat16(xv - __bfloat162float(hi)) : hi;
        }
        g_A0[e] = v;
    }
    for (size_t e = i0; e < (size_t)2 * Bv * KB1; e += stride) g_A1[e] = z;
    for (size_t e = i0; e < (size_t)Bv * Hv; e += stride) { g_c0[e] = 0.f; g_c1[e] = 0.f; }
}

extern "C" void kernel_launch(void* const* d_in, const int* in_sizes, int n_in,
                              void* d_out, int out_size)
{
    const float* x     = (const float*)d_in[0];
    const float* eWih0 = (const float*)d_in[1];
    const float* eWhh0 = (const float*)d_in[2];
    const float* eb0   = (const float*)d_in[3];
    const float* eWih1 = (const float*)d_in[4];
    const float* eWhh1 = (const float*)d_in[5];
    const float* eb1   = (const float*)d_in[6];
    const float* dWih0 = (const float*)d_in[7];
    const float* dWhh0 = (const float*)d_in[8];
    const float* db0   = (const float*)d_in[9];
    const float* dWih1 = (const float*)d_in[10];
    const float* dWhh1 = (const float*)d_in[11];
    const float* db1   = (const float*)d_in[12];
    const float* fW1   = (const float*)d_in[13];
    const float* fb1   = (const float*)d_in[14];
    const float* fW2   = (const float*)d_in[15];
    const float* fb2   = (const float*)d_in[16];
    float* out = (float*)d_out;

    cudaFuncSetAttribute(lstm_main, cudaFuncAttributeMaxDynamicSharedMemorySize, DSM);
    prep_zero<<<512, 256>>>(x);
    prep_x<<<512, 256>>>(x);
    prep_w<<<512, 256>>>(eWih0, eWhh0, 0, 16, 16, 528, KB0, 2048, 1);
    prep_w<<<512, 256>>>(eWih1, eWhh1, 1, 512, 512, 1024, KB1, 2048, 1);
    prep_w<<<512, 256>>>(dWih0, dWhh0, 2, 1, 16, 528, KB0, 2048, 1);
    prep_w<<<512, 256>>>(dWih1, dWhh1, 3, 512, 512, 1024, KB1, 2048, 1);
    prep_w<<<512, 256>>>(fW1, nullptr, 4, 512, 512, 512, KBF, 256, 0);
    lstm_main<<<NCTA, NTHR, DSM>>>(eb0, eb1, db0, db1, fb1, fW2, fb2, out);
}

// round 7
// speedup vs baseline: 1.5719x; 1.5719x over previous
#include <cuda_runtime.h>
#include <cuda_bf16.h>
#include <cstdint>
typedef __nv_bfloat16 bf16;

#define Bv   1024
#define Hv   512
#define TIN  336
#define TOUT 168
#define KB0  1600
#define KB1  3072
#define KBF  1536
#define NCTA 128
#define NTHR 256
#define ACHK 65536    // 1024*64 elems per A chunk block
#define WCHK 131072   // 2048*64 elems per cell-W chunk block
#define FCHK 16384    // 256*64 elems per fc-W chunk block
#define STG_B 32768
#define DSM (1024 + 4*STG_B)

__device__ __align__(128) bf16 g_We0[(size_t)2048*KB0];
__device__ __align__(128) bf16 g_We1[(size_t)2048*KB1];
__device__ __align__(128) bf16 g_Wd0[(size_t)2048*KB0];
__device__ __align__(128) bf16 g_Wd1[(size_t)2048*KB1];
__device__ __align__(128) bf16 g_Wf1[(size_t)256*KBF];
__device__ __align__(128) bf16 g_A0[(size_t)2*Bv*KB0];
__device__ __align__(128) bf16 g_A1[(size_t)2*Bv*KB1];
__device__ __align__(128) bf16 g_xb[(size_t)Bv*TIN*48];
__device__ __align__(128) float g_c0[Bv*Hv];
__device__ __align__(128) float g_c1[Bv*Hv];
__device__ __align__(128) float g_hid[Bv*256];
__device__ unsigned g_cnt = 0;
__device__ volatile unsigned g_gen = 0;

__device__ __forceinline__ float sigf(float x) { return 1.f / (1.f + __expf(-x)); }

__device__ __forceinline__ void gbar() {
    __syncthreads();
    __threadfence();
    if (threadIdx.x == 0) {
        unsigned gen = g_gen;
        if (atomicAdd(&g_cnt, 1u) == (unsigned)(gridDim.x - 1)) {
            g_cnt = 0; __threadfence(); g_gen = gen + 1;
        } else {
            while (g_gen == gen) { __nanosleep(32); }
        }
        __threadfence();
    }
    __syncthreads();
}
__device__ __forceinline__ void mbar_wait(uint32_t mbar, uint32_t parity) {
    uint32_t done = 0;
    while (!done) {
        asm volatile("{\n\t.reg .pred p;\n\t"
            "mbarrier.try_wait.parity.acquire.cta.shared::cta.b64 p, [%1], %2;\n\t"
            "selp.b32 %0,1,0,p;\n\t}" : "=r"(done) : "r"(mbar), "r"(parity) : "memory");
    }
}
__device__ __forceinline__ void bulk_ld(uint32_t dst, const void* src, uint32_t bytes, uint32_t mb) {
    asm volatile("cp.async.bulk.shared::cluster.global.mbarrier::complete_tx::bytes [%0], [%1], %2, [%3];"
                 :: "r"(dst), "l"(src), "r"(bytes), "r"(mb) : "memory");
}
__device__ __forceinline__ void expect_tx(uint32_t mb, uint32_t bytes) {
    asm volatile("mbarrier.arrive.expect_tx.shared.b64 _, [%0], %1;" :: "r"(mb), "r"(bytes) : "memory");
}
__device__ __forceinline__ void ldsm4(uint32_t* r, uint32_t a) {
    asm volatile("ldmatrix.sync.aligned.m8n8.x4.shared.b16 {%0,%1,%2,%3}, [%4];"
        : "=r"(r[0]), "=r"(r[1]), "=r"(r[2]), "=r"(r[3]) : "r"(a));
}
__device__ __forceinline__ void hmma(float* c, const uint32_t* a, uint32_t b0, uint32_t b1) {
    asm volatile("mma.sync.aligned.m16n8k16.row.col.f32.bf16.bf16.f32 "
        "{%0,%1,%2,%3}, {%4,%5,%6,%7}, {%8,%9}, {%0,%1,%2,%3};"
        : "+f"(c[0]), "+f"(c[1]), "+f"(c[2]), "+f"(c[3])
        : "r"(a[0]), "r"(a[1]), "r"(a[2]), "r"(a[3]), "r"(b0), "r"(b1));
}
__device__ __forceinline__ uint32_t swadr(uint32_t base, int row, int colByte) {
    return base + row * 128 + (colByte ^ ((row & 7) << 4));
}
// swizzled triple write into chunk-major A buffer
__device__ __forceinline__ void wtrip(bf16* base, int col, int b, bf16 hi, bf16 lo) {
    #pragma unroll
    for (int s = 0; s < 3; s++) {
        int cc = col + s;
        base[(size_t)(cc >> 6) * ACHK + b * 64 + ((cc & 63) ^ ((b & 7) << 3))] = (s == 1) ? lo : hi;
    }
}

// ---------------- cell phase ----------------
__device__ void cell_tc(char* dyn, unsigned& pb,
    const bf16* Ag, const bf16* Wg, int KB, const float* bias, float* cst,
    bf16* h0d, int h0off, bf16* h1d, bf16* xdst, const bf16* xsrc, int xt)
{
    const int tid = threadIdx.x, cta = blockIdx.x;
    const int b0 = (cta >> 4) * 128, u0 = (cta & 15) * 32, w0 = (cta & 15) * 128;
    const int nCh = KB >> 6;
    uint32_t sm0 = (uint32_t)__cvta_generic_to_shared(dyn);

    auto issue = [&](int kc) {
        int st = kc & 3;
        if (tid == 0) {
            uint32_t mb = sm0 + st * 8;
            expect_tx(mb, 32768u);
            uint32_t d = sm0 + 1024 + st * STG_B;
            bulk_ld(d,         Ag + (size_t)kc * ACHK + b0 * 64, 16384u, mb);
            bulk_ld(d + 16384, Wg + (size_t)kc * WCHK + w0 * 64, 16384u, mb);
        }
    };

    const int lane = tid & 31, warp = tid >> 5;
    const int mi = warp >> 2, nj = warp & 3;
    const int la = lane & 15, lb = (lane >> 4) << 4;
    float acc[4][4][4];
    #pragma unroll
    for (int i = 0; i < 4; i++)
        #pragma unroll
        for (int j = 0; j < 4; j++)
            #pragma unroll
            for (int k = 0; k < 4; k++) acc[i][j][k] = 0.f;

    for (int k = 0; k < 4; k++) issue(k);

    for (int kc = 0; kc < nCh; kc++) {
        int st = kc & 3;
        mbar_wait(sm0 + st * 8, (pb >> st) & 1);
        pb ^= (1u << st);
        uint32_t Ab = sm0 + 1024 + st * STG_B;
        uint32_t Bb = Ab + 16384;
        #pragma unroll
        for (int k16 = 0; k16 < 4; k16++) {
            int cb = lb + k16 * 32;
            uint32_t a[4][4], q0[4], q1[4];
            #pragma unroll
            for (int im = 0; im < 4; im++)
                ldsm4(a[im], swadr(Ab, mi * 64 + im * 16 + la, cb));
            ldsm4(q0, swadr(Bb, nj * 32 + la, cb));
            ldsm4(q1, swadr(Bb, nj * 32 + 16 + la, cb));
            #pragma unroll
            for (int im = 0; im < 4; im++) {
                hmma(acc[im][0], a[im], q0[0], q0[2]);
                hmma(acc[im][1], a[im], q0[1], q0[3]);
                hmma(acc[im][2], a[im], q1[0], q1[2]);
                hmma(acc[im][3], a[im], q1[1], q1[3]);
            }
        }
        __syncthreads();
        if (kc + 4 < nCh) issue(kc + 4);
    }

    const int q = lane & 3, r = lane >> 2;
    #pragma unroll
    for (int im = 0; im < 4; im++)
        #pragma unroll
        for (int jn = 0; jn < 4; jn++) {
            float* c4 = acc[im][jn];
            float x0 = __shfl_xor_sync(0xffffffffu, c4[0], 1);
            float x1 = __shfl_xor_sync(0xffffffffu, c4[1], 1);
            float x2 = __shfl_xor_sync(0xffffffffu, c4[2], 1);
            float x3 = __shfl_xor_sync(0xffffffffu, c4[3], 1);
            int u = u0 + nj * 8 + jn * 2 + (q >> 1);
            int row; float gi, gf, gg, go;
            if ((q & 1) == 0) { row = mi * 64 + im * 16 + r;     gi = c4[0]; gf = c4[1]; gg = x0;    go = x1; }
            else              { row = mi * 64 + im * 16 + r + 8; gi = x2;    gf = x3;    gg = c4[2]; go = c4[3]; }
            int b = b0 + row;
            gi += __ldg(bias + u);
            gf += __ldg(bias + 512 + u);
            gg += __ldg(bias + 1024 + u);
            go += __ldg(bias + 1536 + u);
            float co = cst[(size_t)u * Bv + b];
            float cn = sigf(gf) * co + sigf(gi) * tanhf(gg);
            float h  = sigf(go) * tanhf(cn);
            cst[(size_t)u * Bv + b] = cn;
            bf16 hi = __float2bfloat16(h);
            bf16 lo = __float2bfloat16(h - __bfloat162float(hi));
            wtrip(h0d, h0off + 3 * u, b, hi, lo);
            if (h1d) wtrip(h1d, 1536 + 3 * u, b, hi, lo);
        }

    if (xdst && (cta & 15) == 0) {   // fill x cols 0..47 (chunk 0) of next A0 buffer
        for (int i = tid; i < 128 * 6; i += NTHR) {
            int row = i / 6, seg = i % 6;
            int b = b0 + row;
            uint4* d = (uint4*)(xdst + (size_t)b * 64 + ((seg * 8) ^ ((b & 7) << 3)));
            if (xsrc) *d = *(const uint4*)(xsrc + ((size_t)b * TIN + xt) * 48 + seg * 8);
            else      *d = make_uint4(0, 0, 0, 0);
        }
    }
    __syncthreads();
}

// ---------------- fc1: hid = relu(h1 @ W1^T + b1) ----------------
__device__ void fc_phase(char* dyn, unsigned& pb, const float* fb1, const bf16* A1rd)
{
    const int tid = threadIdx.x, cta = blockIdx.x;
    if (cta >= 64) return;
    const int b0 = (cta >> 3) * 128, n0 = (cta & 7) * 32;
    const int nCh = KBF >> 6;   // 24
    uint32_t sm0 = (uint32_t)__cvta_generic_to_shared(dyn);

    auto issue = [&](int kc) {
        int st = kc & 3;
        if (tid == 0) {
            uint32_t mb = sm0 + st * 8;
            expect_tx(mb, 20480u);
            uint32_t d = sm0 + 1024 + st * STG_B;
            bulk_ld(d,         A1rd + (size_t)(24 + kc) * ACHK + b0 * 64, 16384u, mb);
            bulk_ld(d + 16384, g_Wf1 + (size_t)kc * FCHK + n0 * 64, 4096u, mb);
        }
    };

    const int lane = tid & 31, warp = tid >> 5;
    const int la = lane & 15, lb = (lane >> 4) << 4;
    float acc[4][4];
    #pragma unroll
    for (int j = 0; j < 4; j++)
        #pragma unroll
        for (int k = 0; k < 4; k++) acc[j][k] = 0.f;

    for (int k = 0; k < 4; k++) issue(k);
    for (int kc = 0; kc < nCh; kc++) {
        int st = kc & 3;
        mbar_wait(sm0 + st * 8, (pb >> st) & 1);
        pb ^= (1u << st);
        uint32_t Ab = sm0 + 1024 + st * STG_B;
        uint32_t Bb = Ab + 16384;
        #pragma unroll
        for (int k16 = 0; k16 < 4; k16++) {
            int cb = lb + k16 * 32;
            uint32_t a[4], q0[4], q1[4];
            ldsm4(a, swadr(Ab, warp * 16 + la, cb));
            ldsm4(q0, swadr(Bb, la, cb));
            ldsm4(q1, swadr(Bb, 16 + la, cb));
            hmma(acc[0], a, q0[0], q0[2]);
            hmma(acc[1], a, q0[1], q0[3]);
            hmma(acc[2], a, q1[0], q1[2]);
            hmma(acc[3], a, q1[1], q1[3]);
        }
        __syncthreads();
        if (kc + 4 < nCh) issue(kc + 4);
    }

    #pragma unroll
    for (int jn = 0; jn < 4; jn++) {
        int n = n0 + jn * 8 + (lane & 3) * 2;
        int r0 = b0 + warp * 16 + (lane >> 2);
        g_hid[(size_t)r0 * 256 + n]           = fmaxf(acc[jn][0] + __ldg(fb1 + n), 0.f);
        g_hid[(size_t)r0 * 256 + n + 1]       = fmaxf(acc[jn][1] + __ldg(fb1 + n + 1), 0.f);
        g_hid[(size_t)(r0 + 8) * 256 + n]     = fmaxf(acc[jn][2] + __ldg(fb1 + n), 0.f);
        g_hid[(size_t)(r0 + 8) * 256 + n + 1] = fmaxf(acc[jn][3] + __ldg(fb1 + n + 1), 0.f);
    }
    __syncthreads();
}

// ---------------- pred ----------------
__device__ void pred_phase(int t, float* out, const float* w2, const float* b2, bf16* A0wr)
{
    int b = blockIdx.x * 8 + (threadIdx.x >> 5);
    int lane = threadIdx.x & 31;
    float s = 0.f;
    #pragma unroll 8
    for (int j = lane; j < 256; j += 32)
        s += __ldcg(&g_hid[b * 256 + j]) * __ldg(w2 + j);
    #pragma unroll
    for (int o = 16; o; o >>= 1) s += __shfl_down_sync(0xffffffffu, s, o);
    if (lane == 0) {
        float p = fmaxf(s + __ldg(b2), 0.f);
        out[b * TOUT + t] = p;
        bf16 hi = __float2bfloat16(p);
        bf16 lo = __float2bfloat16(p - __bfloat162float(hi));
        wtrip(A0wr, 0, b, hi, lo);
    }
}

extern __shared__ __align__(1024) char dynsm[];
__global__ void __launch_bounds__(NTHR) lstm_main(
    const float* eb0, const float* eb1, const float* db0, const float* db1,
    const float* fb1, const float* fW2, const float* fb2, float* out)
{
    const int tid = threadIdx.x;
    uint32_t sm0 = (uint32_t)__cvta_generic_to_shared(dynsm);
    if (tid == 0) {
        #pragma unroll
        for (int s = 0; s < 4; s++)
            asm volatile("mbarrier.init.shared.b64 [%0], %1;" :: "r"(sm0 + s * 8), "r"(1u) : "memory");
    }
    __syncthreads();
    unsigned pb = 0;
    const size_t A0SZ = (size_t)Bv * KB0, A1SZ = (size_t)Bv * KB1;

    for (int s = 0; s < TIN; s++) {
        int p = s & 1;
        cell_tc(dynsm, pb, g_A0 + p * A0SZ, g_We0, KB0, eb0, g_c0,
                g_A0 + (p ^ 1) * A0SZ, 48, g_A1 + (p ^ 1) * A1SZ,
                g_A0 + (p ^ 1) * A0SZ, (s + 1 < TIN) ? g_xb : nullptr, s + 1);
        gbar();
        cell_tc(dynsm, pb, g_A1 + (p ^ 1) * A1SZ, g_We1, KB1, eb1, g_c1,
                g_A1 + p * A1SZ, 1536, nullptr, nullptr, nullptr, 0);
        gbar();
    }
    for (int td = 0; td < TOUT; td++) {
        int p = (TIN + td) & 1;
        cell_tc(dynsm, pb, g_A0 + p * A0SZ, g_Wd0, KB0, db0, g_c0,
                g_A0 + (p ^ 1) * A0SZ, 48, g_A1 + (p ^ 1) * A1SZ,
                g_A0 + (p ^ 1) * A0SZ, nullptr, 0);
        gbar();
        cell_tc(dynsm, pb, g_A1 + (p ^ 1) * A1SZ, g_Wd1, KB1, db1, g_c1,
                g_A1 + p * A1SZ, 1536, nullptr, nullptr, nullptr, 0);
        gbar();
        fc_phase(dynsm, pb, fb1, g_A1 + p * A1SZ);
        gbar();
        pred_phase(td, out, fW2, fb2, g_A0 + (p ^ 1) * A0SZ);
        gbar();
    }
}

// ---------------- single merged prep kernel ----------------
__device__ void fill_w(const float* Wih, const float* Whh, bf16* dst,
                       int rows, size_t chk, int Fin, int Fpad, int Kf, int KB, int il)
{
    size_t stride = (size_t)gridDim.x * blockDim.x;
    size_t tot = (size_t)rows * KB;
    for (size_t e = (size_t)blockIdx.x * blockDim.x + threadIdx.x; e < tot; e += stride) {
        int kc = (int)(e / chk);
        int rem = (int)(e - (size_t)kc * chk);
        int rp = rem >> 6, cs = rem & 63;
        int c = cs ^ ((rp & 7) << 3);
        int col = kc * 64 + c;
        int g = il ? ((rp & 3) * 512 + (rp >> 2)) : rp;
        float v = 0.f;
        int inr = (col < 3 * Kf);
        int k = col / 3, slot = col - 3 * k;
        if (inr) {
            if (k < Fin)       v = Wih[(size_t)g * Fin + k];
            else if (k < Fpad) v = 0.f;
            else               v = Whh[(size_t)g * Hv + (k - Fpad)];
        }
        bf16 hi = __float2bfloat16(v);
        bf16 lo = __float2bfloat16(v - __bfloat162float(hi));
        dst[e] = (!inr) ? __float2bfloat16(0.f) : ((slot == 2) ? lo : hi);
    }
}

__global__ void prep_all(const float* x,
    const float* eWih0, const float* eWhh0, const float* eWih1, const float* eWhh1,
    const float* dWih0, const float* dWhh0, const float* dWih1, const float* dWhh1,
    const float* fW1)
{
    size_t stride = (size_t)gridDim.x * blockDim.x;
    size_t i0 = (size_t)blockIdx.x * blockDim.x + threadIdx.x;

    // A0: two chunk-major buffers; buffer 0 gets x_0 triple (swizzled), rest zero
    for (size_t e = i0; e < (size_t)2 * Bv * KB0; e += stride) {
        size_t p = e / ((size_t)Bv * KB0);
        size_t i = e - p * (size_t)Bv * KB0;
        int kc = (int)(i / ACHK);
        int rem = (int)(i - (size_t)kc * ACHK);
        int b = rem >> 6, cs = rem & 63;
        int c = cs ^ ((b & 7) << 3);
        int col = kc * 64 + c;
        bf16 v = __float2bfloat16(0.f);
        if (p == 0 && col < 48) {
            int k = col / 3, slot = col - 3 * k;
            float xv = x[(size_t)b * (TIN * 16) + k];
            bf16 hi = __float2bfloat16(xv);
            v = (slot == 1) ? __float2bfloat16(xv - __bfloat162float(hi)) : hi;
        }
        g_A0[e] = v;
    }
    for (size_t e = i0; e < (size_t)2 * Bv * KB1; e += stride) g_A1[e] = __float2bfloat16(0.f);
    for (size_t e = i0; e < (size_t)Bv * Hv; e += stride) { g_c0[e] = 0.f; g_c1[e] = 0.f; }

    // x triple, linear [b][t][48]
    for (size_t e = i0; e < (size_t)Bv * TIN * 48; e += stride) {
        int col = (int)(e % 48);
        size_t row = e / 48;
        int k = col / 3, slot = col - 3 * k;
        float v = x[row * 16 + k];
        bf16 hi = __float2bfloat16(v);
        g_xb[e] = (slot == 1) ? __float2bfloat16(v - __bfloat162float(hi)) : hi;
    }

    fill_w(eWih0, eWhh0, g_We0, 2048, WCHK, 16, 16, 528, KB0, 1);
    fill_w(eWih1, eWhh1, g_We1, 2048, WCHK, 512, 512, 1024, KB1, 1);
    fill_w(dWih0, dWhh0, g_Wd0, 2048, WCHK, 1, 16, 528, KB0, 1);
    fill_w(dWih1, dWhh1, g_Wd1, 2048, WCHK, 512, 512, 1024, KB1, 1);
    fill_w(fW1, nullptr, g_Wf1, 256, FCHK, 512, 512, 512, KBF, 0);
}

extern "C" void kernel_launch(void* const* d_in, const int* in_sizes, int n_in,
                              void* d_out, int out_size)
{
    const float* x     = (const float*)d_in[0];
    const float* eWih0 = (const float*)d_in[1];
    const float* eWhh0 = (const float*)d_in[2];
    const float* eb0   = (const float*)d_in[3];
    const float* eWih1 = (const float*)d_in[4];
    const float* eWhh1 = (const float*)d_in[5];
    const float* eb1   = (const float*)d_in[6];
    const float* dWih0 = (const float*)d_in[7];
    const float* dWhh0 = (const float*)d_in[8];
    const float* db0   = (const float*)d_in[9];
    const float* dWih1 = (const float*)d_in[10];
    const float* dWhh1 = (const float*)d_in[11];
    const float* db1   = (const float*)d_in[12];
    const float* fW1   = (const float*)d_in[13];
    const float* fb1   = (const float*)d_in[14];
    const float* fW2   = (const float*)d_in[15];
    const float* fb2   = (const float*)d_in[16];
    float* out = (float*)d_out;

    cudaFuncSetAttribute(lstm_main, cudaFuncAttributeMaxDynamicSharedMemorySize, DSM);
    prep_all<<<512, 256>>>(x, eWih0, eWhh0, eWih1, eWhh1, dWih0, dWhh0, dWih1, dWhh1, fW1);
    lstm_main<<<NCTA, NTHR, DSM>>>(eb0, eb1, db0, db1, fb1, fW2, fb2, out);
}

// round 8
// speedup vs baseline: 4.2393x; 2.6969x over previous
#include <cuda_runtime.h>
#include <cuda_bf16.h>
#include <cstdint>
typedef __nv_bfloat16 bf16;

#define Bv   1024
#define Hv   512
#define TIN  336
#define TOUT 168
#define KB0  576
#define KB1  1024
#define KBF  512
#define NCTA 128
#define NTHR 512
#define ACHK 65536    // 1024 rows * 64 cols per A chunk block
#define WCHK 131072   // 2048 rows * 64
#define FCHK 16384    // 256 rows * 64
#define STG_B 32768
#define DSM (1024 + 4*STG_B)

__device__ __align__(128) bf16 g_We0[(size_t)2048*KB0];
__device__ __align__(128) bf16 g_We1[(size_t)2048*KB1];
__device__ __align__(128) bf16 g_Wd0[(size_t)2048*KB0];
__device__ __align__(128) bf16 g_Wd1[(size_t)2048*KB1];
__device__ __align__(128) bf16 g_Wf1[(size_t)256*KBF];
__device__ __align__(128) bf16 g_A0[(size_t)2*Bv*KB0];
__device__ __align__(128) bf16 g_A1[(size_t)2*Bv*KB1];
__device__ __align__(128) bf16 g_xb[(size_t)Bv*TIN*16];
__device__ __align__(128) float g_c0[Bv*Hv];   // [u][b]
__device__ __align__(128) float g_c1[Bv*Hv];   // [u][b]
__device__ __align__(128) float g_hid[Bv*256];
__device__ unsigned g_cnt = 0;
__device__ volatile unsigned g_gen = 0;

__device__ __forceinline__ float sigf(float x) { return 1.f / (1.f + __expf(-x)); }

__device__ __forceinline__ void gbar() {
    __syncthreads();
    __threadfence();
    if (threadIdx.x == 0) {
        unsigned gen = g_gen;
        if (atomicAdd(&g_cnt, 1u) == (unsigned)(gridDim.x - 1)) {
            g_cnt = 0; __threadfence(); g_gen = gen + 1;
        } else {
            while (g_gen == gen) { __nanosleep(32); }
        }
        __threadfence();
    }
    __syncthreads();
}
__device__ __forceinline__ void mbar_wait(uint32_t mbar, uint32_t parity) {
    uint32_t done = 0;
    while (!done) {
        asm volatile("{\n\t.reg .pred p;\n\t"
            "mbarrier.try_wait.parity.acquire.cta.shared::cta.b64 p, [%1], %2;\n\t"
            "selp.b32 %0,1,0,p;\n\t}" : "=r"(done) : "r"(mbar), "r"(parity) : "memory");
    }
}
__device__ __forceinline__ void bulk_ld(uint32_t dst, const void* src, uint32_t bytes, uint32_t mb) {
    asm volatile("cp.async.bulk.shared::cluster.global.mbarrier::complete_tx::bytes [%0], [%1], %2, [%3];"
                 :: "r"(dst), "l"(src), "r"(bytes), "r"(mb) : "memory");
}
__device__ __forceinline__ void expect_tx(uint32_t mb, uint32_t bytes) {
    asm volatile("mbarrier.arrive.expect_tx.shared.b64 _, [%0], %1;" :: "r"(mb), "r"(bytes) : "memory");
}
__device__ __forceinline__ void ldsm4(uint32_t* r, uint32_t a) {
    asm volatile("ldmatrix.sync.aligned.m8n8.x4.shared.b16 {%0,%1,%2,%3}, [%4];"
        : "=r"(r[0]), "=r"(r[1]), "=r"(r[2]), "=r"(r[3]) : "r"(a));
}
__device__ __forceinline__ void hmma(float* c, const uint32_t* a, uint32_t b0, uint32_t b1) {
    asm volatile("mma.sync.aligned.m16n8k16.row.col.f32.bf16.bf16.f32 "
        "{%0,%1,%2,%3}, {%4,%5,%6,%7}, {%8,%9}, {%0,%1,%2,%3};"
        : "+f"(c[0]), "+f"(c[1]), "+f"(c[2]), "+f"(c[3])
        : "r"(a[0]), "r"(a[1]), "r"(a[2]), "r"(a[3]), "r"(b0), "r"(b1));
}
__device__ __forceinline__ uint32_t swadr(uint32_t base, int row, int colByte) {
    return base + row * 128 + (colByte ^ ((row & 7) << 4));
}
__device__ __forceinline__ void wr1(bf16* base, int col, int b, bf16 v) {
    base[(size_t)(col >> 6) * ACHK + b * 64 + ((col & 63) ^ ((b & 7) << 3))] = v;
}

// ---------------- cell phase: C[128b x 128(4u+gate)] = A @ W'^T + LSTM cell ----
__device__ void cell_tc(char* dyn, unsigned& pb,
    const bf16* Ag, const bf16* Wg, int KB, const float* bias, float* cst,
    bf16* h0d, int h0off, bf16* h1d,
    bf16* xdst, const bf16* xsrc, int xt,
    const float* hid, const float* w2, const float* b2p, float* out, int t)
{
    const int tid = threadIdx.x, cta = blockIdx.x;
    const int b0 = (cta >> 4) * 128, u0 = (cta & 15) * 32, w0 = (cta & 15) * 128;
    const int nCh = KB >> 6;
    uint32_t sm0 = (uint32_t)__cvta_generic_to_shared(dyn);

    auto issue = [&](int kc) {
        if (tid == 0) {
            int st = kc & 3;
            uint32_t mb = sm0 + st * 8;
            expect_tx(mb, 32768u);
            uint32_t d = sm0 + 1024 + st * STG_B;
            bulk_ld(d,         Ag + (size_t)kc * ACHK + b0 * 64, 16384u, mb);
            bulk_ld(d + 16384, Wg + (size_t)kc * WCHK + w0 * 64, 16384u, mb);
        }
    };
    #pragma unroll
    for (int k = 0; k < 4; k++) if (k < nCh) issue(k);

    // inline pred (decoder cell0): pred(t-1) from g_hid, patched into smem chunk 0 col 0
    float myp = 0.f;
    const int prow = tid >> 2, pq = tid & 3;
    if (hid != nullptr && t > 0) {
        const float* hr = hid + (size_t)(b0 + prow) * 256 + pq * 64;
        const float* wr = w2 + pq * 64;
        float s = 0.f;
        #pragma unroll 8
        for (int j = 0; j < 64; j++) s += __ldcg(hr + j) * __ldg(wr + j);
        s += __shfl_xor_sync(0xffffffffu, s, 1);
        s += __shfl_xor_sync(0xffffffffu, s, 2);
        myp = fmaxf(s + __ldg(b2p), 0.f);
        if (pq == 0 && (cta & 15) == 0) out[(size_t)(b0 + prow) * TOUT + (t - 1)] = myp;
    }

    const int lane = tid & 31, warp = tid >> 5;
    const int mi = warp >> 2, nj = warp & 3;
    const int la = lane & 15, lb = (lane >> 4) << 4;
    float acc[2][4][4];
    #pragma unroll
    for (int i = 0; i < 2; i++)
        #pragma unroll
        for (int j = 0; j < 4; j++)
            #pragma unroll
            for (int k = 0; k < 4; k++) acc[i][j][k] = 0.f;

    for (int kc = 0; kc < nCh; kc++) {
        int st = kc & 3;
        mbar_wait(sm0 + st * 8, (pb >> st) & 1);
        pb ^= (1u << st);
        if (hid != nullptr && kc == 0) {
            if (t > 0 && pq == 0)
                *(bf16*)(dyn + 1024 + prow * 128 + (0 ^ ((prow & 7) << 4))) = __float2bfloat16(myp);
            __syncthreads();
        }
        uint32_t Ab = sm0 + 1024 + st * STG_B, Bb = Ab + 16384;
        #pragma unroll
        for (int k16 = 0; k16 < 4; k16++) {
            int cb = lb + k16 * 32;
            uint32_t a0[4], a1[4], q[4];
            ldsm4(a0, swadr(Ab, mi * 32 + la, cb));
            ldsm4(a1, swadr(Ab, mi * 32 + 16 + la, cb));
            ldsm4(q, swadr(Bb, nj * 32 + la, cb));
            hmma(acc[0][0], a0, q[0], q[2]); hmma(acc[0][1], a0, q[1], q[3]);
            hmma(acc[1][0], a1, q[0], q[2]); hmma(acc[1][1], a1, q[1], q[3]);
            ldsm4(q, swadr(Bb, nj * 32 + 16 + la, cb));
            hmma(acc[0][2], a0, q[0], q[2]); hmma(acc[0][3], a0, q[1], q[3]);
            hmma(acc[1][2], a1, q[0], q[2]); hmma(acc[1][3], a1, q[1], q[3]);
        }
        __syncthreads();
        if (kc + 4 < nCh) issue(kc + 4);
    }

    const int qq = lane & 3, r = lane >> 2;
    #pragma unroll
    for (int im = 0; im < 2; im++)
        #pragma unroll
        for (int jn = 0; jn < 4; jn++) {
            float* c4 = acc[im][jn];
            float x0 = __shfl_xor_sync(0xffffffffu, c4[0], 1);
            float x1 = __shfl_xor_sync(0xffffffffu, c4[1], 1);
            float x2 = __shfl_xor_sync(0xffffffffu, c4[2], 1);
            float x3 = __shfl_xor_sync(0xffffffffu, c4[3], 1);
            int u = u0 + nj * 8 + jn * 2 + (qq >> 1);
            int row; float gi, gf, gg, go;
            if ((qq & 1) == 0) { row = mi * 32 + im * 16 + r;     gi = c4[0]; gf = c4[1]; gg = x0;    go = x1; }
            else               { row = mi * 32 + im * 16 + r + 8; gi = x2;    gf = x3;    gg = c4[2]; go = c4[3]; }
            int b = b0 + row;
            gi += __ldg(bias + u);
            gf += __ldg(bias + 512 + u);
            gg += __ldg(bias + 1024 + u);
            go += __ldg(bias + 1536 + u);
            float co = cst[(size_t)u * Bv + b];
            float cn = sigf(gf) * co + sigf(gi) * tanhf(gg);
            float h  = sigf(go) * tanhf(cn);
            cst[(size_t)u * Bv + b] = cn;
            bf16 hb = __float2bfloat16(h);
            wr1(h0d, h0off + u, b, hb);
            if (h1d) wr1(h1d, u, b, hb);
        }

    if (xdst && (cta & 15) == 0) {   // x cols 0..15 of next A0 buffer (chunk 0)
        for (int i = tid; i < 256; i += NTHR) {
            int row = i >> 1, seg = i & 1;
            int b = b0 + row;
            uint4* d = (uint4*)(xdst + (size_t)b * 64 + ((seg * 8) ^ ((b & 7) << 3)));
            if (xsrc) *d = *(const uint4*)(xsrc + ((size_t)b * TIN + xt) * 16 + seg * 8);
            else      *d = make_uint4(0, 0, 0, 0);
        }
    }
    __syncthreads();
}

// ---------------- fc1: hid = relu(h1 @ W1^T + b1), 128 CTAs, 64x32 tiles ----
__device__ void fc_phase(char* dyn, unsigned& pb, const float* fb1, const bf16* A1rd)
{
    const int tid = threadIdx.x, cta = blockIdx.x;
    const int b0 = (cta >> 3) * 64, n0 = (cta & 7) * 32;
    const int nCh = 8;
    uint32_t sm0 = (uint32_t)__cvta_generic_to_shared(dyn);

    auto issue = [&](int kc) {
        if (tid == 0) {
            int st = kc & 3;
            uint32_t mb = sm0 + st * 8;
            expect_tx(mb, 12288u);
            uint32_t d = sm0 + 1024 + st * STG_B;
            bulk_ld(d,        A1rd + (size_t)(8 + kc) * ACHK + b0 * 64, 8192u, mb);
            bulk_ld(d + 8192, g_Wf1 + (size_t)kc * FCHK + n0 * 64, 4096u, mb);
        }
    };
    #pragma unroll
    for (int k = 0; k < 4; k++) issue(k);

    const int lane = tid & 31, warp = tid >> 5;
    const int la = lane & 15, lb = (lane >> 4) << 4;
    const int mi = warp >> 1, nj = warp & 1;
    float acc[2][4];
    #pragma unroll
    for (int j = 0; j < 2; j++)
        #pragma unroll
        for (int k = 0; k < 4; k++) acc[j][k] = 0.f;

    for (int kc = 0; kc < nCh; kc++) {
        int st = kc & 3;
        mbar_wait(sm0 + st * 8, (pb >> st) & 1);
        pb ^= (1u << st);
        if (warp < 8) {
            uint32_t Ab = sm0 + 1024 + st * STG_B, Bb = Ab + 8192;
            #pragma unroll
            for (int k16 = 0; k16 < 4; k16++) {
                int cb = lb + k16 * 32;
                uint32_t a[4], q[4];
                ldsm4(a, swadr(Ab, mi * 16 + la, cb));
                ldsm4(q, swadr(Bb, nj * 16 + la, cb));
                hmma(acc[0], a, q[0], q[2]);
                hmma(acc[1], a, q[1], q[3]);
            }
        }
        __syncthreads();
        if (kc + 4 < nCh) issue(kc + 4);
    }
    if (warp < 8) {
        #pragma unroll
        for (int jb = 0; jb < 2; jb++) {
            int n = n0 + nj * 16 + jb * 8 + (lane & 3) * 2;
            int r0 = b0 + mi * 16 + (lane >> 2);
            g_hid[(size_t)r0 * 256 + n]           = fmaxf(acc[jb][0] + __ldg(fb1 + n), 0.f);
            g_hid[(size_t)r0 * 256 + n + 1]       = fmaxf(acc[jb][1] + __ldg(fb1 + n + 1), 0.f);
            g_hid[(size_t)(r0 + 8) * 256 + n]     = fmaxf(acc[jb][2] + __ldg(fb1 + n), 0.f);
            g_hid[(size_t)(r0 + 8) * 256 + n + 1] = fmaxf(acc[jb][3] + __ldg(fb1 + n + 1), 0.f);
        }
    }
    __syncthreads();
}

extern __shared__ __align__(1024) char dynsm[];
__global__ void __launch_bounds__(NTHR, 1) lstm_main(
    const float* eb0, const float* eb1, const float* db0, const float* db1,
    const float* fb1, const float* fW2, const float* fb2, float* out)
{
    const int tid = threadIdx.x;
    uint32_t sm0 = (uint32_t)__cvta_generic_to_shared(dynsm);
    if (tid == 0) {
        #pragma unroll
        for (int s = 0; s < 4; s++)
            asm volatile("mbarrier.init.shared.b64 [%0], %1;" :: "r"(sm0 + s * 8), "r"(1u) : "memory");
    }
    __syncthreads();
    unsigned pb = 0;
    const size_t A0SZ = (size_t)Bv * KB0, A1SZ = (size_t)Bv * KB1;

    // encoder: phase i runs L0(i) and L1(i-1)
    for (int i = 0; i <= TIN; i++) {
        if (i < TIN)
            cell_tc(dynsm, pb, g_A0 + (i & 1) * A0SZ, g_We0, KB0, eb0, g_c0,
                    g_A0 + ((i + 1) & 1) * A0SZ, 16, g_A1 + (i & 1) * A1SZ,
                    g_A0 + ((i + 1) & 1) * A0SZ, (i + 1 < TIN) ? g_xb : nullptr, i + 1,
                    nullptr, nullptr, nullptr, nullptr, 0);
        if (i > 0)
            cell_tc(dynsm, pb, g_A1 + ((i + 1) & 1) * A1SZ, g_We1, KB1, eb1, g_c1,
                    g_A1 + (i & 1) * A1SZ, 512, nullptr,
                    nullptr, nullptr, 0, nullptr, nullptr, nullptr, nullptr, 0);
        gbar();
    }

    int p = 0, q = 0;
    for (int td = 0; td < TOUT; td++) {
        cell_tc(dynsm, pb, g_A0 + p * A0SZ, g_Wd0, KB0, db0, g_c0,
                g_A0 + (p ^ 1) * A0SZ, 16, g_A1 + q * A1SZ,
                g_A0 + (p ^ 1) * A0SZ, nullptr, 0,
                g_hid, fW2, fb2, out, td);
        gbar();
        cell_tc(dynsm, pb, g_A1 + q * A1SZ, g_Wd1, KB1, db1, g_c1,
                g_A1 + (q ^ 1) * A1SZ, 512, nullptr,
                nullptr, nullptr, 0, nullptr, nullptr, nullptr, nullptr, 0);
        gbar();
        fc_phase(dynsm, pb, fb1, g_A1 + (q ^ 1) * A1SZ);
        gbar();
        p ^= 1; q ^= 1;
    }

    // final pred t = 167
    int gid = blockIdx.x * NTHR + tid;
    if (gid < 4096) {
        int b = gid >> 2, pq4 = gid & 3;
        const float* hr = g_hid + (size_t)b * 256 + pq4 * 64;
        const float* wr = fW2 + pq4 * 64;
        float s = 0.f;
        #pragma unroll 8
        for (int j = 0; j < 64; j++) s += __ldcg(hr + j) * __ldg(wr + j);
        s += __shfl_xor_sync(0xffffffffu, s, 1);
        s += __shfl_xor_sync(0xffffffffu, s, 2);
        if (pq4 == 0) out[(size_t)b * TOUT + 167] = fmaxf(s + __ldg(fb2), 0.f);
    }
}

// ---------------- prep ----------------
__device__ void fill_w(const float* Wih, const float* Whh, bf16* dst,
                       int rows, size_t chk, int Fin, int Fpad, int Kf, int KB, int il)
{
    size_t stride = (size_t)gridDim.x * blockDim.x;
    size_t tot = (size_t)rows * KB;
    for (size_t e = (size_t)blockIdx.x * blockDim.x + threadIdx.x; e < tot; e += stride) {
        int kc = (int)(e / chk);
        int rem = (int)(e - (size_t)kc * chk);
        int rp = rem >> 6, cs = rem & 63;
        int col = kc * 64 + (cs ^ ((rp & 7) << 3));
        int g = il ? ((rp & 3) * 512 + (rp >> 2)) : rp;
        float v = 0.f;
        if (col < Fpad)      v = (col < Fin) ? Wih[(size_t)g * Fin + col] : 0.f;
        else if (col < Kf)   v = Whh[(size_t)g * Hv + (col - Fpad)];
        dst[e] = __float2bfloat16(v);
    }
}

__global__ void prep_all(const float* x,
    const float* eWih0, const float* eWhh0, const float* eWih1, const float* eWhh1,
    const float* dWih0, const float* dWhh0, const float* dWih1, const float* dWhh1,
    const float* fW1)
{
    size_t stride = (size_t)gridDim.x * blockDim.x;
    size_t i0 = (size_t)blockIdx.x * blockDim.x + threadIdx.x;

    for (size_t e = i0; e < (size_t)2 * Bv * KB0; e += stride) {
        size_t pz = e / ((size_t)Bv * KB0);
        size_t i = e - pz * (size_t)Bv * KB0;
        int kc = (int)(i / ACHK);
        int rem = (int)(i - (size_t)kc * ACHK);
        int b = rem >> 6, cs = rem & 63;
        int col = kc * 64 + (cs ^ ((b & 7) << 3));
        float v = 0.f;
        if (pz == 0 && col < 16) v = x[(size_t)b * (TIN * 16) + col];
        g_A0[e] = __float2bfloat16(v);
    }
    for (size_t e = i0; e < (size_t)2 * Bv * KB1; e += stride) g_A1[e] = __float2bfloat16(0.f);
    for (size_t e = i0; e < (size_t)Bv * Hv; e += stride) { g_c0[e] = 0.f; g_c1[e] = 0.f; }
    for (size_t e = i0; e < (size_t)Bv * TIN * 16; e += stride)
        g_xb[e] = __float2bfloat16(x[e]);

    fill_w(eWih0, eWhh0, g_We0, 2048, WCHK, 16, 16, 528, KB0, 1);
    fill_w(eWih1, eWhh1, g_We1, 2048, WCHK, 512, 512, 1024, KB1, 1);
    fill_w(dWih0, dWhh0, g_Wd0, 2048, WCHK, 1, 16, 528, KB0, 1);
    fill_w(dWih1, dWhh1, g_Wd1, 2048, WCHK, 512, 512, 1024, KB1, 1);
    fill_w(fW1, nullptr, g_Wf1, 256, FCHK, 512, 512, 512, KBF, 0);
}

extern "C" void kernel_launch(void* const* d_in, const int* in_sizes, int n_in,
                              void* d_out, int out_size)
{
    const float* x     = (const float*)d_in[0];
    const float* eWih0 = (const float*)d_in[1];
    const float* eWhh0 = (const float*)d_in[2];
    const float* eb0   = (const float*)d_in[3];
    const float* eWih1 = (const float*)d_in[4];
    const float* eWhh1 = (const float*)d_in[5];
    const float* eb1   = (const float*)d_in[6];
    const float* dWih0 = (const float*)d_in[7];
    const float* dWhh0 = (const float*)d_in[8];
    const float* db0   = (const float*)d_in[9];
    const float* dWih1 = (const float*)d_in[10];
    const float* dWhh1 = (const float*)d_in[11];
    const float* db1   = (const float*)d_in[12];
    const float* fW1   = (const float*)d_in[13];
    const float* fb1   = (const float*)d_in[14];
    const float* fW2   = (const float*)d_in[15];
    const float* fb2   = (const float*)d_in[16];
    float* out = (float*)d_out;

    cudaFuncSetAttribute(lstm_main, cudaFuncAttributeMaxDynamicSharedMemorySize, DSM);
    prep_all<<<512, 256>>>(x, eWih0, eWhh0, eWih1, eWhh1, dWih0, dWhh0, dWih1, dWhh1, fW1);
    lstm_main<<<NCTA, NTHR, DSM>>>(eb0, eb1, db0, db1, fb1, fW2, fb2, out);
}

// round 9
// speedup vs baseline: 4.3375x; 1.0232x over previous
#include <cuda_runtime.h>
#include <cuda_bf16.h>
#include <cstdint>
typedef __nv_bfloat16 bf16;

#define Bv   1024
#define Hv   512
#define TIN  336
#define TOUT 168
#define KB0  576
#define KB1  1024
#define KBF  512
#define NCTA 128
#define NTHR 512
#define NST  6
#define ACHK 65536
#define WCHK 131072
#define FCHK 16384
#define STG_B 32768
#define DSM (1024 + NST*STG_B)

__device__ __align__(128) bf16 g_We0[(size_t)2048*KB0];
__device__ __align__(128) bf16 g_We1[(size_t)2048*KB1];
__device__ __align__(128) bf16 g_Wd0[(size_t)2048*KB0];
__device__ __align__(128) bf16 g_Wd1[(size_t)2048*KB1];
__device__ __align__(128) bf16 g_Wf1[(size_t)256*KBF];
__device__ __align__(128) bf16 g_A0[(size_t)2*Bv*KB0];
__device__ __align__(128) bf16 g_A1[(size_t)2*Bv*KB1];
__device__ __align__(128) bf16 g_xb[(size_t)Bv*TIN*16];
__device__ __align__(128) float g_c0[Bv*Hv];
__device__ __align__(128) float g_c1[Bv*Hv];
__device__ __align__(128) float g_hid[Bv*256];
__device__ unsigned g_cnt = 0;
__device__ volatile unsigned g_gen = 0;

struct PS { unsigned pf, pe, nIss, nCon; };

__device__ __forceinline__ float sigf(float x) { return 1.f / (1.f + __expf(-x)); }

__device__ __forceinline__ void gbar() {
    __syncthreads();
    __threadfence();
    if (threadIdx.x == 0) {
        unsigned gen = g_gen;
        if (atomicAdd(&g_cnt, 1u) == (unsigned)(gridDim.x - 1)) {
            g_cnt = 0; __threadfence(); g_gen = gen + 1;
        } else {
            while (g_gen == gen) { __nanosleep(32); }
        }
        __threadfence();
    }
    __syncthreads();
}
__device__ __forceinline__ void mbar_wait(uint32_t mbar, uint32_t parity) {
    uint32_t done = 0;
    while (!done) {
        asm volatile("{\n\t.reg .pred p;\n\t"
            "mbarrier.try_wait.parity.acquire.cta.shared::cta.b64 p, [%1], %2;\n\t"
            "selp.b32 %0,1,0,p;\n\t}" : "=r"(done) : "r"(mbar), "r"(parity) : "memory");
    }
}
__device__ __forceinline__ void mbar_arrive(uint32_t mbar) {
    asm volatile("mbarrier.arrive.release.cta.shared::cta.b64 _, [%0];" :: "r"(mbar) : "memory");
}
__device__ __forceinline__ void bulk_ld(uint32_t dst, const void* src, uint32_t bytes, uint32_t mb) {
    asm volatile("cp.async.bulk.shared::cluster.global.mbarrier::complete_tx::bytes [%0], [%1], %2, [%3];"
                 :: "r"(dst), "l"(src), "r"(bytes), "r"(mb) : "memory");
}
__device__ __forceinline__ void expect_tx(uint32_t mb, uint32_t bytes) {
    asm volatile("mbarrier.arrive.expect_tx.shared.b64 _, [%0], %1;" :: "r"(mb), "r"(bytes) : "memory");
}
__device__ __forceinline__ void ldsm4(uint32_t* r, uint32_t a) {
    asm volatile("ldmatrix.sync.aligned.m8n8.x4.shared.b16 {%0,%1,%2,%3}, [%4];"
        : "=r"(r[0]), "=r"(r[1]), "=r"(r[2]), "=r"(r[3]) : "r"(a));
}
__device__ __forceinline__ void hmma(float* c, const uint32_t* a, uint32_t b0, uint32_t b1) {
    asm volatile("mma.sync.aligned.m16n8k16.row.col.f32.bf16.bf16.f32 "
        "{%0,%1,%2,%3}, {%4,%5,%6,%7}, {%8,%9}, {%0,%1,%2,%3};"
        : "+f"(c[0]), "+f"(c[1]), "+f"(c[2]), "+f"(c[3])
        : "r"(a[0]), "r"(a[1]), "r"(a[2]), "r"(a[3]), "r"(b0), "r"(b1));
}
__device__ __forceinline__ uint32_t swadr(uint32_t base, int row, int colByte) {
    return base + row * 128 + (colByte ^ ((row & 7) << 4));
}
__device__ __forceinline__ void wr1(bf16* base, int col, int b, bf16 v) {
    base[(size_t)(col >> 6) * ACHK + b * 64 + ((col & 63) ^ ((b & 7) << 3))] = v;
}

// ---------------- cell phase ----------------
__device__ void cell_tc(char* dyn, PS& ps,
    const bf16* Ag, bf16* Agw, const bf16* Wg, int KB, const float* bias, float* cst,
    bf16* h0d, int h0off, bf16* h1d,
    bf16* xdst, const bf16* xsrc, int xt,
    const float* hid, const float* w2, const float* b2p, float* out, int t)
{
    const int tid = threadIdx.x, cta = blockIdx.x;
    const int b0 = (cta >> 4) * 128, u0 = (cta & 15) * 32, w0 = (cta & 15) * 128;
    const int nCh = KB >> 6;
    uint32_t sm0 = (uint32_t)__cvta_generic_to_shared(dyn);

    // decoder cell0: pred(t-1) -> gmem A col0 BEFORE any TMA issue
    if (hid != nullptr) {
        if (t > 0) {
            const int prow = tid >> 2, pq = tid & 3;
            const float* hr = hid + (size_t)(b0 + prow) * 256 + pq * 64;
            const float* wr = w2 + pq * 64;
            float s = 0.f;
            #pragma unroll 8
            for (int j = 0; j < 64; j++) s += __ldcg(hr + j) * __ldg(wr + j);
            s += __shfl_xor_sync(0xffffffffu, s, 1);
            s += __shfl_xor_sync(0xffffffffu, s, 2);
            float myp = fmaxf(s + __ldg(b2p), 0.f);
            if (pq == 0) {
                if ((cta & 15) == 0) out[(size_t)(b0 + prow) * TOUT + (t - 1)] = myp;
                wr1(Agw, 0, b0 + prow, __float2bfloat16(myp));
            }
            __threadfence();
        }
        __syncthreads();
    }

    auto prod = [&](int kc) {
        if (tid == 0) {
            unsigned st = ps.nIss % NST;
            if (ps.nIss >= NST) {
                mbar_wait(sm0 + 64 + st * 8, (ps.pe >> st) & 1);
                ps.pe ^= 1u << st;
            }
            uint32_t mb = sm0 + st * 8;
            expect_tx(mb, 32768u);
            uint32_t d = sm0 + 1024 + st * STG_B;
            bulk_ld(d,         Ag + (size_t)kc * ACHK + b0 * 64, 16384u, mb);
            bulk_ld(d + 16384, Wg + (size_t)kc * WCHK + w0 * 64, 16384u, mb);
        }
        ps.nIss++;
    };
    #pragma unroll
    for (int k = 0; k < NST; k++) prod(k);

    const int lane = tid & 31, warp = tid >> 5;
    const int mi = warp >> 2, nj = warp & 3;
    const int la = lane & 15, lb = (lane >> 4) << 4;
    float acc[2][4][4];
    #pragma unroll
    for (int i = 0; i < 2; i++)
        #pragma unroll
        for (int j = 0; j < 4; j++)
            #pragma unroll
            for (int k = 0; k < 4; k++) acc[i][j][k] = 0.f;

    for (int kc = 0; kc < nCh; kc++) {
        unsigned st = ps.nCon % NST;
        mbar_wait(sm0 + st * 8, (ps.pf >> st) & 1);
        ps.pf ^= 1u << st;
        uint32_t Ab = sm0 + 1024 + st * STG_B, Bb = Ab + 16384;
        #pragma unroll
        for (int k16 = 0; k16 < 4; k16++) {
            int cb = lb + k16 * 32;
            uint32_t a0[4], a1[4], q[4];
            ldsm4(a0, swadr(Ab, mi * 32 + la, cb));
            ldsm4(a1, swadr(Ab, mi * 32 + 16 + la, cb));
            ldsm4(q, swadr(Bb, nj * 32 + la, cb));
            hmma(acc[0][0], a0, q[0], q[2]); hmma(acc[0][1], a0, q[1], q[3]);
            hmma(acc[1][0], a1, q[0], q[2]); hmma(acc[1][1], a1, q[1], q[3]);
            ldsm4(q, swadr(Bb, nj * 32 + 16 + la, cb));
            hmma(acc[0][2], a0, q[0], q[2]); hmma(acc[0][3], a0, q[1], q[3]);
            hmma(acc[1][2], a1, q[0], q[2]); hmma(acc[1][3], a1, q[1], q[3]);
        }
        if (lane == 0) mbar_arrive(sm0 + 64 + st * 8);
        ps.nCon++;
        if (NST + kc < nCh) prod(NST + kc);
    }

    const int qq = lane & 3, r = lane >> 2;
    #pragma unroll
    for (int im = 0; im < 2; im++)
        #pragma unroll
        for (int jn = 0; jn < 4; jn++) {
            float* c4 = acc[im][jn];
            float x0 = __shfl_xor_sync(0xffffffffu, c4[0], 1);
            float x1 = __shfl_xor_sync(0xffffffffu, c4[1], 1);
            float x2 = __shfl_xor_sync(0xffffffffu, c4[2], 1);
            float x3 = __shfl_xor_sync(0xffffffffu, c4[3], 1);
            int u = u0 + nj * 8 + jn * 2 + (qq >> 1);
            int row; float gi, gf, gg, go;
            if ((qq & 1) == 0) { row = mi * 32 + im * 16 + r;     gi = c4[0]; gf = c4[1]; gg = x0;    go = x1; }
            else               { row = mi * 32 + im * 16 + r + 8; gi = x2;    gf = x3;    gg = c4[2]; go = c4[3]; }
            int b = b0 + row;
            gi += __ldg(bias + u);
            gf += __ldg(bias + 512 + u);
            gg += __ldg(bias + 1024 + u);
            go += __ldg(bias + 1536 + u);
            float co = cst[(size_t)u * Bv + b];
            float cn = sigf(gf) * co + sigf(gi) * tanhf(gg);
            float h  = sigf(go) * tanhf(cn);
            cst[(size_t)u * Bv + b] = cn;
            bf16 hb = __float2bfloat16(h);
            wr1(h0d, h0off + u, b, hb);
            if (h1d) wr1(h1d, u, b, hb);
        }

    if (xdst && (cta & 15) == 0) {
        for (int i = tid; i < 256; i += NTHR) {
            int row = i >> 1, seg = i & 1;
            int b = b0 + row;
            uint4* d = (uint4*)(xdst + (size_t)b * 64 + ((seg * 8) ^ ((b & 7) << 3)));
            if (xsrc) *d = *(const uint4*)(xsrc + ((size_t)b * TIN + xt) * 16 + seg * 8);
            else      *d = make_uint4(0, 0, 0, 0);
        }
    }
}

// ---------------- fc1 ----------------
__device__ void fc_phase(char* dyn, PS& ps, const float* fb1, const bf16* A1rd)
{
    const int tid = threadIdx.x, cta = blockIdx.x;
    const int b0 = (cta >> 3) * 64, n0 = (cta & 7) * 32;
    const int nCh = 8;
    uint32_t sm0 = (uint32_t)__cvta_generic_to_shared(dyn);

    auto prod = [&](int kc) {
        if (tid == 0) {
            unsigned st = ps.nIss % NST;
            if (ps.nIss >= NST) {
                mbar_wait(sm0 + 64 + st * 8, (ps.pe >> st) & 1);
                ps.pe ^= 1u << st;
            }
            uint32_t mb = sm0 + st * 8;
            expect_tx(mb, 12288u);
            uint32_t d = sm0 + 1024 + st * STG_B;
            bulk_ld(d,        A1rd + (size_t)(8 + kc) * ACHK + b0 * 64, 8192u, mb);
            bulk_ld(d + 8192, g_Wf1 + (size_t)kc * FCHK + n0 * 64, 4096u, mb);
        }
        ps.nIss++;
    };
    #pragma unroll
    for (int k = 0; k < NST; k++) prod(k);

    const int lane = tid & 31, warp = tid >> 5;
    const int la = lane & 15, lb = (lane >> 4) << 4;
    const int mi = warp >> 1, nj = warp & 1;
    float acc[2][4];
    #pragma unroll
    for (int j = 0; j < 2; j++)
        #pragma unroll
        for (int k = 0; k < 4; k++) acc[j][k] = 0.f;

    for (int kc = 0; kc < nCh; kc++) {
        unsigned st = ps.nCon % NST;
        mbar_wait(sm0 + st * 8, (ps.pf >> st) & 1);
        ps.pf ^= 1u << st;
        if (warp < 8) {
            uint32_t Ab = sm0 + 1024 + st * STG_B, Bb = Ab + 8192;
            #pragma unroll
            for (int k16 = 0; k16 < 4; k16++) {
                int cb = lb + k16 * 32;
                uint32_t a[4], q[4];
                ldsm4(a, swadr(Ab, mi * 16 + la, cb));
                ldsm4(q, swadr(Bb, nj * 16 + la, cb));
                hmma(acc[0], a, q[0], q[2]);
                hmma(acc[1], a, q[1], q[3]);
            }
        }
        if (lane == 0) mbar_arrive(sm0 + 64 + st * 8);
        ps.nCon++;
        if (NST + kc < nCh) prod(NST + kc);
    }
    if (warp < 8) {
        #pragma unroll
        for (int jb = 0; jb < 2; jb++) {
            int n = n0 + nj * 16 + jb * 8 + (lane & 3) * 2;
            int r0 = b0 + mi * 16 + (lane >> 2);
            g_hid[(size_t)r0 * 256 + n]           = fmaxf(acc[jb][0] + __ldg(fb1 + n), 0.f);
            g_hid[(size_t)r0 * 256 + n + 1]       = fmaxf(acc[jb][1] + __ldg(fb1 + n + 1), 0.f);
            g_hid[(size_t)(r0 + 8) * 256 + n]     = fmaxf(acc[jb][2] + __ldg(fb1 + n), 0.f);
            g_hid[(size_t)(r0 + 8) * 256 + n + 1] = fmaxf(acc[jb][3] + __ldg(fb1 + n + 1), 0.f);
        }
    }
}

extern __shared__ __align__(1024) char dynsm[];
__global__ void __launch_bounds__(NTHR, 1) lstm_main(
    const float* eb0, const float* eb1, const float* db0, const float* db1,
    const float* fb1, const float* fW2, const float* fb2, float* out)
{
    const int tid = threadIdx.x;
    uint32_t sm0 = (uint32_t)__cvta_generic_to_shared(dynsm);
    if (tid == 0) {
        #pragma unroll
        for (int s = 0; s < NST; s++) {
            asm volatile("mbarrier.init.shared.b64 [%0], %1;" :: "r"(sm0 + s * 8), "r"(1u) : "memory");
            asm volatile("mbarrier.init.shared.b64 [%0], %1;" :: "r"(sm0 + 64 + s * 8), "r"(16u) : "memory");
        }
    }
    __syncthreads();
    PS ps; ps.pf = 0; ps.pe = 0; ps.nIss = 0; ps.nCon = 0;
    const size_t A0SZ = (size_t)Bv * KB0, A1SZ = (size_t)Bv * KB1;

    for (int i = 0; i <= TIN; i++) {
        if (i < TIN)
            cell_tc(dynsm, ps, g_A0 + (i & 1) * A0SZ, nullptr, g_We0, KB0, eb0, g_c0,
                    g_A0 + ((i + 1) & 1) * A0SZ, 16, g_A1 + (i & 1) * A1SZ,
                    g_A0 + ((i + 1) & 1) * A0SZ, (i + 1 < TIN) ? g_xb : nullptr, i + 1,
                    nullptr, nullptr, nullptr, nullptr, 0);
        if (i > 0)
            cell_tc(dynsm, ps, g_A1 + ((i + 1) & 1) * A1SZ, nullptr, g_We1, KB1, eb1, g_c1,
                    g_A1 + (i & 1) * A1SZ, 512, nullptr,
                    nullptr, nullptr, 0, nullptr, nullptr, nullptr, nullptr, 0);
        gbar();
    }

    int p = 0, q = 0;
    for (int td = 0; td < TOUT; td++) {
        cell_tc(dynsm, ps, g_A0 + p * A0SZ, g_A0 + p * A0SZ, g_Wd0, KB0, db0, g_c0,
                g_A0 + (p ^ 1) * A0SZ, 16, g_A1 + q * A1SZ,
                g_A0 + (p ^ 1) * A0SZ, nullptr, 0,
                g_hid, fW2, fb2, out, td);
        gbar();
        cell_tc(dynsm, ps, g_A1 + q * A1SZ, nullptr, g_Wd1, KB1, db1, g_c1,
                g_A1 + (q ^ 1) * A1SZ, 512, nullptr,
                nullptr, nullptr, 0, nullptr, nullptr, nullptr, nullptr, 0);
        gbar();
        fc_phase(dynsm, ps, fb1, g_A1 + (q ^ 1) * A1SZ);
        gbar();
        p ^= 1; q ^= 1;
    }

    int gid = blockIdx.x * NTHR + tid;
    if (gid < 4096) {
        int b = gid >> 2, pq4 = gid & 3;
        const float* hr = g_hid + (size_t)b * 256 + pq4 * 64;
        const float* wr = fW2 + pq4 * 64;
        float s = 0.f;
        #pragma unroll 8
        for (int j = 0; j < 64; j++) s += __ldcg(hr + j) * __ldg(wr + j);
        s += __shfl_xor_sync(0xffffffffu, s, 1);
        s += __shfl_xor_sync(0xffffffffu, s, 2);
        if (pq4 == 0) out[(size_t)b * TOUT + 167] = fmaxf(s + __ldg(fb2), 0.f);
    }
}

// ---------------- prep ----------------
__device__ void fill_w(const float* Wih, const float* Whh, bf16* dst,
                       int rows, size_t chk, int Fin, int Fpad, int Kf, int KB, int il)
{
    size_t stride = (size_t)gridDim.x * blockDim.x;
    size_t tot = (size_t)rows * KB;
    for (size_t e = (size_t)blockIdx.x * blockDim.x + threadIdx.x; e < tot; e += stride) {
        int kc = (int)(e / chk);
        int rem = (int)(e - (size_t)kc * chk);
        int rp = rem >> 6, cs = rem & 63;
        int col = kc * 64 + (cs ^ ((rp & 7) << 3));
        int g = il ? ((rp & 3) * 512 + (rp >> 2)) : rp;
        float v = 0.f;
        if (col < Fpad)      v = (col < Fin) ? Wih[(size_t)g * Fin + col] : 0.f;
        else if (col < Kf)   v = Whh[(size_t)g * Hv + (col - Fpad)];
        dst[e] = __float2bfloat16(v);
    }
}

__global__ void prep_all(const float* x,
    const float* eWih0, const float* eWhh0, const float* eWih1, const float* eWhh1,
    const float* dWih0, const float* dWhh0, const float* dWih1, const float* dWhh1,
    const float* fW1)
{
    size_t stride = (size_t)gridDim.x * blockDim.x;
    size_t i0 = (size_t)blockIdx.x * blockDim.x + threadIdx.x;

    for (size_t e = i0; e < (size_t)2 * Bv * KB0; e += stride) {
        size_t pz = e / ((size_t)Bv * KB0);
        size_t i = e - pz * (size_t)Bv * KB0;
        int kc = (int)(i / ACHK);
        int rem = (int)(i - (size_t)kc * ACHK);
        int b = rem >> 6, cs = rem & 63;
        int col = kc * 64 + (cs ^ ((b & 7) << 3));
        float v = 0.f;
        if (pz == 0 && col < 16) v = x[(size_t)b * (TIN * 16) + col];
        g_A0[e] = __float2bfloat16(v);
    }
    for (size_t e = i0; e < (size_t)2 * Bv * KB1; e += stride) g_A1[e] = __float2bfloat16(0.f);
    for (size_t e = i0; e < (size_t)Bv * Hv; e += stride) { g_c0[e] = 0.f; g_c1[e] = 0.f; }
    for (size_t e = i0; e < (size_t)Bv * TIN * 16; e += stride)
        g_xb[e] = __float2bfloat16(x[e]);

    fill_w(eWih0, eWhh0, g_We0, 2048, WCHK, 16, 16, 528, KB0, 1);
    fill_w(eWih1, eWhh1, g_We1, 2048, WCHK, 512, 512, 1024, KB1, 1);
    fill_w(dWih0, dWhh0, g_Wd0, 2048, WCHK, 1, 16, 528, KB0, 1);
    fill_w(dWih1, dWhh1, g_Wd1, 2048, WCHK, 512, 512, 1024, KB1, 1);
    fill_w(fW1, nullptr, g_Wf1, 256, FCHK, 512, 512, 512, KBF, 0);
}

extern "C" void kernel_launch(void* const* d_in, const int* in_sizes, int n_in,
                              void* d_out, int out_size)
{
    const float* x     = (const float*)d_in[0];
    const float* eWih0 = (const float*)d_in[1];
    const float* eWhh0 = (const float*)d_in[2];
    const float* eb0   = (const float*)d_in[3];
    const float* eWih1 = (const float*)d_in[4];
    const float* eWhh1 = (const float*)d_in[5];
    const float* eb1   = (const float*)d_in[6];
    const float* dWih0 = (const float*)d_in[7];
    const float* dWhh0 = (const float*)d_in[8];
    const float* db0   = (const float*)d_in[9];
    const float* dWih1 = (const float*)d_in[10];
    const float* dWhh1 = (const float*)d_in[11];
    const float* db1   = (const float*)d_in[12];
    const float* fW1   = (const float*)d_in[13];
    const float* fb1   = (const float*)d_in[14];
    const float* fW2   = (const float*)d_in[15];
    const float* fb2   = (const float*)d_in[16];
    float* out = (float*)d_out;

    cudaFuncSetAttribute(lstm_main, cudaFuncAttributeMaxDynamicSharedMemorySize, DSM);
    prep_all<<<512, 256>>>(x, eWih0, eWhh0, eWih1, eWhh1, dWih0, dWhh0, dWih1, dWhh1, fW1);
    lstm_main<<<NCTA, NTHR, DSM>>>(eb0, eb1, db0, db1, fb1, fW2, fb2, out);
}

// round 10
// speedup vs baseline: 4.3422x; 1.0011x over previous
#include <cuda_runtime.h>
#include <cuda_bf16.h>
#include <cstdint>
typedef __nv_bfloat16 bf16;

#define Bv   1024
#define Hv   512
#define TIN  336
#define TOUT 168
#define KB0  576
#define KB1  1024
#define KBF  512
#define NCTA 128
#define NTHR 512
#define NST  6
#define ACHK 65536
#define WCHK 131072
#define FCHK 16384
#define STG_B 32768
#define DSM (1024 + NST*STG_B)

__device__ __align__(128) bf16 g_We0[(size_t)2048*KB0];
__device__ __align__(128) bf16 g_We1[(size_t)2048*KB1];
__device__ __align__(128) bf16 g_Wd0[(size_t)2048*KB0];
__device__ __align__(128) bf16 g_Wd1[(size_t)2048*KB1];
__device__ __align__(128) bf16 g_Wf1[(size_t)256*KBF];
__device__ __align__(128) bf16 g_A0[(size_t)2*Bv*KB0];
__device__ __align__(128) bf16 g_A1[(size_t)2*Bv*KB1];
__device__ __align__(128) bf16 g_xb[(size_t)Bv*TIN*16];
__device__ __align__(128) float g_c0[Bv*Hv];
__device__ __align__(128) float g_c1[Bv*Hv];
__device__ __align__(128) float g_hid[Bv*256];
__device__ unsigned g_cnt = 0;
__device__ volatile unsigned g_gen = 0;

struct PS { unsigned pf, pe, nIss, nCon; };

__device__ __forceinline__ float sigf(float x) { return 1.f / (1.f + __expf(-x)); }

__device__ __forceinline__ void gbar() {
    __syncthreads();
    __threadfence();
    if (threadIdx.x == 0) {
        unsigned gen = g_gen;
        if (atomicAdd(&g_cnt, 1u) == (unsigned)(gridDim.x - 1)) {
            g_cnt = 0; __threadfence(); g_gen = gen + 1;
        } else {
            while (g_gen == gen) { __nanosleep(32); }
        }
        __threadfence();
    }
    __syncthreads();
}
__device__ __forceinline__ void mbar_wait(uint32_t mbar, uint32_t parity) {
    uint32_t done = 0;
    while (!done) {
        asm volatile("{\n\t.reg .pred p;\n\t"
            "mbarrier.try_wait.parity.acquire.cta.shared::cta.b64 p, [%1], %2;\n\t"
            "selp.b32 %0,1,0,p;\n\t}" : "=r"(done) : "r"(mbar), "r"(parity) : "memory");
    }
}
__device__ __forceinline__ void mbar_arrive(uint32_t mbar) {
    asm volatile("mbarrier.arrive.release.cta.shared::cta.b64 _, [%0];" :: "r"(mbar) : "memory");
}
__device__ __forceinline__ void bulk_ld(uint32_t dst, const void* src, uint32_t bytes, uint32_t mb) {
    asm volatile("cp.async.bulk.shared::cluster.global.mbarrier::complete_tx::bytes [%0], [%1], %2, [%3];"
                 :: "r"(dst), "l"(src), "r"(bytes), "r"(mb) : "memory");
}
__device__ __forceinline__ void expect_tx(uint32_t mb, uint32_t bytes) {
    asm volatile("mbarrier.arrive.expect_tx.shared.b64 _, [%0], %1;" :: "r"(mb), "r"(bytes) : "memory");
}
__device__ __forceinline__ void ldsm4(uint32_t* r, uint32_t a) {
    asm volatile("ldmatrix.sync.aligned.m8n8.x4.shared.b16 {%0,%1,%2,%3}, [%4];"
        : "=r"(r[0]), "=r"(r[1]), "=r"(r[2]), "=r"(r[3]) : "r"(a));
}
__device__ __forceinline__ void hmma(float* c, const uint32_t* a, uint32_t b0, uint32_t b1) {
    asm volatile("mma.sync.aligned.m16n8k16.row.col.f32.bf16.bf16.f32 "
        "{%0,%1,%2,%3}, {%4,%5,%6,%7}, {%8,%9}, {%0,%1,%2,%3};"
        : "+f"(c[0]), "+f"(c[1]), "+f"(c[2]), "+f"(c[3])
        : "r"(a[0]), "r"(a[1]), "r"(a[2]), "r"(a[3]), "r"(b0), "r"(b1));
}
__device__ __forceinline__ uint32_t swadr(uint32_t base, int row, int colByte) {
    return base + row * 128 + (colByte ^ ((row & 7) << 4));
}
__device__ __forceinline__ void wr1(bf16* base, int col, int b, bf16 v) {
    base[(size_t)(col >> 6) * ACHK + b * 64 + ((col & 63) ^ ((b & 7) << 3))] = v;
}

// ---------------- cell phase ----------------
__device__ void cell_tc(char* dyn, PS& ps,
    const bf16* Ag, bf16* Agw, const bf16* Wg, int KB, const float* bias, float* cst,
    bf16* h0d, int h0off, bf16* h1d,
    bf16* xdst, const bf16* xsrc, int xt,
    const float* hid, const float* w2, const float* b2p, float* out, int t)
{
    const int tid = threadIdx.x, cta = blockIdx.x;
    const int b0 = (cta >> 4) * 128, u0 = (cta & 15) * 32, w0 = (cta & 15) * 128;
    const int nCh = KB >> 6;
    uint32_t sm0 = (uint32_t)__cvta_generic_to_shared(dyn);

    // decoder cell0: pred(t-1) -> gmem A col0 BEFORE any TMA issue
    if (hid != nullptr) {
        if (t > 0) {
            const int prow = tid >> 2, pq = tid & 3;
            const float* hr = hid + (size_t)(b0 + prow) * 256 + pq * 64;
            const float* wr = w2 + pq * 64;
            float s = 0.f;
            #pragma unroll 8
            for (int j = 0; j < 64; j++) s += __ldcg(hr + j) * __ldg(wr + j);
            s += __shfl_xor_sync(0xffffffffu, s, 1);
            s += __shfl_xor_sync(0xffffffffu, s, 2);
            float myp = fmaxf(s + __ldg(b2p), 0.f);
            if (pq == 0) {
                if ((cta & 15) == 0) out[(size_t)(b0 + prow) * TOUT + (t - 1)] = myp;
                wr1(Agw, 0, b0 + prow, __float2bfloat16(myp));
            }
            __threadfence();
        }
        __syncthreads();
    }

    auto prod = [&](int kc) {
        if (tid == 0) {
            unsigned st = ps.nIss % NST;
            if (ps.nIss >= NST) {
                mbar_wait(sm0 + 64 + st * 8, (ps.pe >> st) & 1);
                ps.pe ^= 1u << st;
            }
            uint32_t mb = sm0 + st * 8;
            expect_tx(mb, 32768u);
            uint32_t d = sm0 + 1024 + st * STG_B;
            bulk_ld(d,         Ag + (size_t)kc * ACHK + b0 * 64, 16384u, mb);
            bulk_ld(d + 16384, Wg + (size_t)kc * WCHK + w0 * 64, 16384u, mb);
        }
        ps.nIss++;
    };
    #pragma unroll
    for (int k = 0; k < NST; k++) prod(k);

    const int lane = tid & 31, warp = tid >> 5;
    const int mi = warp >> 2, nj = warp & 3;
    const int la = lane & 15, lb = (lane >> 4) << 4;
    float acc[2][4][4];
    #pragma unroll
    for (int i = 0; i < 2; i++)
        #pragma unroll
        for (int j = 0; j < 4; j++)
            #pragma unroll
            for (int k = 0; k < 4; k++) acc[i][j][k] = 0.f;

    for (int kc = 0; kc < nCh; kc++) {
        unsigned st = ps.nCon % NST;
        mbar_wait(sm0 + st * 8, (ps.pf >> st) & 1);
        ps.pf ^= 1u << st;
        uint32_t Ab = sm0 + 1024 + st * STG_B, Bb = Ab + 16384;
        #pragma unroll
        for (int k16 = 0; k16 < 4; k16++) {
            int cb = lb + k16 * 32;
            uint32_t a0[4], a1[4], q[4];
            ldsm4(a0, swadr(Ab, mi * 32 + la, cb));
            ldsm4(a1, swadr(Ab, mi * 32 + 16 + la, cb));
            ldsm4(q, swadr(Bb, nj * 32 + la, cb));
            hmma(acc[0][0], a0, q[0], q[2]); hmma(acc[0][1], a0, q[1], q[3]);
            hmma(acc[1][0], a1, q[0], q[2]); hmma(acc[1][1], a1, q[1], q[3]);
            ldsm4(q, swadr(Bb, nj * 32 + 16 + la, cb));
            hmma(acc[0][2], a0, q[0], q[2]); hmma(acc[0][3], a0, q[1], q[3]);
            hmma(acc[1][2], a1, q[0], q[2]); hmma(acc[1][3], a1, q[1], q[3]);
        }
        if (lane == 0) mbar_arrive(sm0 + 64 + st * 8);
        ps.nCon++;
        if (NST + kc < nCh) prod(NST + kc);
    }

    const int qq = lane & 3, r = lane >> 2;
    #pragma unroll
    for (int im = 0; im < 2; im++)
        #pragma unroll
        for (int jn = 0; jn < 4; jn++) {
            float* c4 = acc[im][jn];
            float x0 = __shfl_xor_sync(0xffffffffu, c4[0], 1);
            float x1 = __shfl_xor_sync(0xffffffffu, c4[1], 1);
            float x2 = __shfl_xor_sync(0xffffffffu, c4[2], 1);
            float x3 = __shfl_xor_sync(0xffffffffu, c4[3], 1);
            int u = u0 + nj * 8 + jn * 2 + (qq >> 1);
            int row; float gi, gf, gg, go;
            if ((qq & 1) == 0) { row = mi * 32 + im * 16 + r;     gi = c4[0]; gf = c4[1]; gg = x0;    go = x1; }
            else               { row = mi * 32 + im * 16 + r + 8; gi = x2;    gf = x3;    gg = c4[2]; go = c4[3]; }
            int b = b0 + row;
            gi += __ldg(bias + u);
            gf += __ldg(bias + 512 + u);
            gg += __ldg(bias + 1024 + u);
            go += __ldg(bias + 1536 + u);
            float co = cst[(size_t)u * Bv + b];
            float cn = sigf(gf) * co + sigf(gi) * tanhf(gg);
            float h  = sigf(go) * tanhf(cn);
            cst[(size_t)u * Bv + b] = cn;
            bf16 hb = __float2bfloat16(h);
            wr1(h0d, h0off + u, b, hb);
            if (h1d) wr1(h1d, u, b, hb);
        }

    if (xdst && (cta & 15) == 0) {
        for (int i = tid; i < 256; i += NTHR) {
            int row = i >> 1, seg = i & 1;
            int b = b0 + row;
            uint4* d = (uint4*)(xdst + (size_t)b * 64 + ((seg * 8) ^ ((b & 7) << 3)));
            if (xsrc) *d = *(const uint4*)(xsrc + ((size_t)b * TIN + xt) * 16 + seg * 8);
            else      *d = make_uint4(0, 0, 0, 0);
        }
    }
}

// ---------------- fc1 ----------------
__device__ void fc_phase(char* dyn, PS& ps, const float* fb1, const bf16* A1rd)
{
    const int tid = threadIdx.x, cta = blockIdx.x;
    const int b0 = (cta >> 3) * 64, n0 = (cta & 7) * 32;
    const int nCh = 8;
    uint32_t sm0 = (uint32_t)__cvta_generic_to_shared(dyn);

    auto prod = [&](int kc) {
        if (tid == 0) {
            unsigned st = ps.nIss % NST;
            if (ps.nIss >= NST) {
                mbar_wait(sm0 + 64 + st * 8, (ps.pe >> st) & 1);
                ps.pe ^= 1u << st;
            }
            uint32_t mb = sm0 + st * 8;
            expect_tx(mb, 12288u);
            uint32_t d = sm0 + 1024 + st * STG_B;
            bulk_ld(d,        A1rd + (size_t)(8 + kc) * ACHK + b0 * 64, 8192u, mb);
            bulk_ld(d + 8192, g_Wf1 + (size_t)kc * FCHK + n0 * 64, 4096u, mb);
        }
        ps.nIss++;
    };
    #pragma unroll
    for (int k = 0; k < NST; k++) prod(k);

    const int lane = tid & 31, warp = tid >> 5;
    const int la = lane & 15, lb = (lane >> 4) << 4;
    const int mi = warp >> 1, nj = warp & 1;
    float acc[2][4];
    #pragma unroll
    for (int j = 0; j < 2; j++)
        #pragma unroll
        for (int k = 0; k < 4; k++) acc[j][k] = 0.f;

    for (int kc = 0; kc < nCh; kc++) {
        unsigned st = ps.nCon % NST;
        mbar_wait(sm0 + st * 8, (ps.pf >> st) & 1);
        ps.pf ^= 1u << st;
        if (warp < 8) {
            uint32_t Ab = sm0 + 1024 + st * STG_B, Bb = Ab + 8192;
            #pragma unroll
            for (int k16 = 0; k16 < 4; k16++) {
                int cb = lb + k16 * 32;
                uint32_t a[4], q[4];
                ldsm4(a, swadr(Ab, mi * 16 + la, cb));
                ldsm4(q, swadr(Bb, nj * 16 + la, cb));
                hmma(acc[0], a, q[0], q[2]);
                hmma(acc[1], a, q[1], q[3]);
            }
        }
        if (lane == 0) mbar_arrive(sm0 + 64 + st * 8);
        ps.nCon++;
        if (NST + kc < nCh) prod(NST + kc);
    }
    if (warp < 8) {
        #pragma unroll
        for (int jb = 0; jb < 2; jb++) {
            int n = n0 + nj * 16 + jb * 8 + (lane & 3) * 2;
            int r0 = b0 + mi * 16 + (lane >> 2);
            g_hid[(size_t)r0 * 256 + n]           = fmaxf(acc[jb][0] + __ldg(fb1 + n), 0.f);
            g_hid[(size_t)r0 * 256 + n + 1]       = fmaxf(acc[jb][1] + __ldg(fb1 + n + 1), 0.f);
            g_hid[(size_t)(r0 + 8) * 256 + n]     = fmaxf(acc[jb][2] + __ldg(fb1 + n), 0.f);
            g_hid[(size_t)(r0 + 8) * 256 + n + 1] = fmaxf(acc[jb][3] + __ldg(fb1 + n + 1), 0.f);
        }
    }
}

extern __shared__ __align__(1024) char dynsm[];
__global__ void __launch_bounds__(NTHR, 1) lstm_main(
    const float* eb0, const float* eb1, const float* db0, const float* db1,
    const float* fb1, const float* fW2, const float* fb2, float* out)
{
    const int tid = threadIdx.x;
    uint32_t sm0 = (uint32_t)__cvta_generic_to_shared(dynsm);
    if (tid == 0) {
        #pragma unroll
        for (int s = 0; s < NST; s++) {
            asm volatile("mbarrier.init.shared.b64 [%0], %1;" :: "r"(sm0 + s * 8), "r"(1u) : "memory");
            asm volatile("mbarrier.init.shared.b64 [%0], %1;" :: "r"(sm0 + 64 + s * 8), "r"(16u) : "memory");
        }
    }
    __syncthreads();
    PS ps; ps.pf = 0; ps.pe = 0; ps.nIss = 0; ps.nCon = 0;
    const size_t A0SZ = (size_t)Bv * KB0, A1SZ = (size_t)Bv * KB1;

    for (int i = 0; i <= TIN; i++) {
        if (i < TIN)
            cell_tc(dynsm, ps, g_A0 + (i & 1) * A0SZ, nullptr, g_We0, KB0, eb0, g_c0,
                    g_A0 + ((i + 1) & 1) * A0SZ, 16, g_A1 + (i & 1) * A1SZ,
                    g_A0 + ((i + 1) & 1) * A0SZ, (i + 1 < TIN) ? g_xb : nullptr, i + 1,
                    nullptr, nullptr, nullptr, nullptr, 0);
        if (i > 0)
            cell_tc(dynsm, ps, g_A1 + ((i + 1) & 1) * A1SZ, nullptr, g_We1, KB1, eb1, g_c1,
                    g_A1 + (i & 1) * A1SZ, 512, nullptr,
                    nullptr, nullptr, 0, nullptr, nullptr, nullptr, nullptr, 0);
        gbar();
    }

    int p = 0, q = 0;
    for (int td = 0; td < TOUT; td++) {
        cell_tc(dynsm, ps, g_A0 + p * A0SZ, g_A0 + p * A0SZ, g_Wd0, KB0, db0, g_c0,
                g_A0 + (p ^ 1) * A0SZ, 16, g_A1 + q * A1SZ,
                g_A0 + (p ^ 1) * A0SZ, nullptr, 0,
                g_hid, fW2, fb2, out, td);
        gbar();
        cell_tc(dynsm, ps, g_A1 + q * A1SZ, nullptr, g_Wd1, KB1, db1, g_c1,
                g_A1 + (q ^ 1) * A1SZ, 512, nullptr,
                nullptr, nullptr, 0, nullptr, nullptr, nullptr, nullptr, 0);
        gbar();
        fc_phase(dynsm, ps, fb1, g_A1 + (q ^ 1) * A1SZ);
        gbar();
        p ^= 1; q ^= 1;
    }

    int gid = blockIdx.x * NTHR + tid;
    if (gid < 4096) {
        int b = gid >> 2, pq4 = gid & 3;
        const float* hr = g_hid + (size_t)b * 256 + pq4 * 64;
        const float* wr = fW2 + pq4 * 64;
        float s = 0.f;
        #pragma unroll 8
        for (int j = 0; j < 64; j++) s += __ldcg(hr + j) * __ldg(wr + j);
        s += __shfl_xor_sync(0xffffffffu, s, 1);
        s += __shfl_xor_sync(0xffffffffu, s, 2);
        if (pq4 == 0) out[(size_t)b * TOUT + 167] = fmaxf(s + __ldg(fb2), 0.f);
    }
}

// ---------------- prep ----------------
__device__ void fill_w(const float* Wih, const float* Whh, bf16* dst,
                       int rows, size_t chk, int Fin, int Fpad, int Kf, int KB, int il)
{
    size_t stride = (size_t)gridDim.x * blockDim.x;
    size_t tot = (size_t)rows * KB;
    for (size_t e = (size_t)blockIdx.x * blockDim.x + threadIdx.x; e < tot; e += stride) {
        int kc = (int)(e / chk);
        int rem = (int)(e - (size_t)kc * chk);
        int rp = rem >> 6, cs = rem & 63;
        int col = kc * 64 + (cs ^ ((rp & 7) << 3));
        int g = il ? ((rp & 3) * 512 + (rp >> 2)) : rp;
        float v = 0.f;
        if (col < Fpad)      v = (col < Fin) ? Wih[(size_t)g * Fin + col] : 0.f;
        else if (col < Kf)   v = Whh[(size_t)g * Hv + (col - Fpad)];
        dst[e] = __float2bfloat16(v);
    }
}

__global__ void prep_all(const float* x,
    const float* eWih0, const float* eWhh0, const float* eWih1, const float* eWhh1,
    const float* dWih0, const float* dWhh0, const float* dWih1, const float* dWhh1,
    const float* fW1)
{
    size_t stride = (size_t)gridDim.x * blockDim.x;
    size_t i0 = (size_t)blockIdx.x * blockDim.x + threadIdx.x;

    for (size_t e = i0; e < (size_t)2 * Bv * KB0; e += stride) {
        size_t pz = e / ((size_t)Bv * KB0);
        size_t i = e - pz * (size_t)Bv * KB0;
        int kc = (int)(i / ACHK);
        int rem = (int)(i - (size_t)kc * ACHK);
        int b = rem >> 6, cs = rem & 63;
        int col = kc * 64 + (cs ^ ((b & 7) << 3));
        float v = 0.f;
        if (pz == 0 && col < 16) v = x[(size_t)b * (TIN * 16) + col];
        g_A0[e] = __float2bfloat16(v);
    }
    for (size_t e = i0; e < (size_t)2 * Bv * KB1; e += stride) g_A1[e] = __float2bfloat16(0.f);
    for (size_t e = i0; e < (size_t)Bv * Hv; e += stride) { g_c0[e] = 0.f; g_c1[e] = 0.f; }
    for (size_t e = i0; e < (size_t)Bv * TIN * 16; e += stride)
        g_xb[e] = __float2bfloat16(x[e]);

    fill_w(eWih0, eWhh0, g_We0, 2048, WCHK, 16, 16, 528, KB0, 1);
    fill_w(eWih1, eWhh1, g_We1, 2048, WCHK, 512, 512, 1024, KB1, 1);
    fill_w(dWih0, dWhh0, g_Wd0, 2048, WCHK, 1, 16, 528, KB0, 1);
    fill_w(dWih1, dWhh1, g_Wd1, 2048, WCHK, 512, 512, 1024, KB1, 1);
    fill_w(fW1, nullptr, g_Wf1, 256, FCHK, 512, 512, 512, KBF, 0);
}

extern "C" void kernel_launch(void* const* d_in, const int* in_sizes, int n_in,
                              void* d_out, int out_size)
{
    const float* x     = (const float*)d_in[0];
    const float* eWih0 = (const float*)d_in[1];
    const float* eWhh0 = (const float*)d_in[2];
    const float* eb0   = (const float*)d_in[3];
    const float* eWih1 = (const float*)d_in[4];
    const float* eWhh1 = (const float*)d_in[5];
    const float* eb1   = (const float*)d_in[6];
    const float* dWih0 = (const float*)d_in[7];
    const float* dWhh0 = (const float*)d_in[8];
    const float* db0   = (const float*)d_in[9];
    const float* dWih1 = (const float*)d_in[10];
    const float* dWhh1 = (const float*)d_in[11];
    const float* db1   = (const float*)d_in[12];
    const float* fW1   = (const float*)d_in[13];
    const float* fb1   = (const float*)d_in[14];
    const float* fW2   = (const float*)d_in[15];
    const float* fb2   = (const float*)d_in[16];
    float* out = (float*)d_out;

    cudaFuncSetAttribute(lstm_main, cudaFuncAttributeMaxDynamicSharedMemorySize, DSM);
    prep_all<<<512, 256>>>(x, eWih0, eWhh0, eWih1, eWhh1, dWih0, dWhh0, dWih1, dWhh1, fW1);
    lstm_main<<<NCTA, NTHR, DSM>>>(eb0, eb1, db0, db1, fb1, fW2, fb2, out);
}

// round 11
// speedup vs baseline: 4.3454x; 1.0007x over previous
#include <cuda_runtime.h>
#include <cuda_bf16.h>
#include <cstdint>
typedef __nv_bfloat16 bf16;

#define Bv   1024
#define Hv   512
#define TIN  336
#define TOUT 168
#define KB0  576
#define KB1  1024
#define KBF  512
#define NCTA 128
#define NTHR 512
#define NST  6
#define ACHK 65536
#define WCHK 131072
#define FCHK 16384
#define STG_B 32768
#define DSM (1024 + NST*STG_B)

__device__ __align__(128) bf16 g_We0[(size_t)2048*KB0];
__device__ __align__(128) bf16 g_We1[(size_t)2048*KB1];
__device__ __align__(128) bf16 g_Wd0[(size_t)2048*KB0];
__device__ __align__(128) bf16 g_Wd1[(size_t)2048*KB1];
__device__ __align__(128) bf16 g_Wf1[(size_t)256*KBF];
__device__ __align__(128) bf16 g_A0[(size_t)2*Bv*KB0];
__device__ __align__(128) bf16 g_A1[(size_t)2*Bv*KB1];
__device__ __align__(128) bf16 g_xb[(size_t)Bv*TIN*16];
__device__ __align__(128) float g_c0[Bv*Hv];
__device__ __align__(128) float g_c1[Bv*Hv];
__device__ __align__(128) float g_hid[Bv*256];
__device__ unsigned g_cnt = 0;
__device__ volatile unsigned g_gen = 0;

struct PS { unsigned pf, pe, nIss, nCon; };

__device__ __forceinline__ float sigf(float x) { return 1.f / (1.f + __expf(-x)); }

__device__ __forceinline__ void gbar() {
    __syncthreads();
    __threadfence();
    if (threadIdx.x == 0) {
        unsigned gen = g_gen;
        if (atomicAdd(&g_cnt, 1u) == (unsigned)(gridDim.x - 1)) {
            g_cnt = 0; __threadfence(); g_gen = gen + 1;
        } else {
            while (g_gen == gen) { __nanosleep(32); }
        }
        __threadfence();
    }
    __syncthreads();
}
__device__ __forceinline__ void mbar_wait(uint32_t mbar, uint32_t parity) {
    uint32_t done = 0;
    while (!done) {
        asm volatile("{\n\t.reg .pred p;\n\t"
            "mbarrier.try_wait.parity.acquire.cta.shared::cta.b64 p, [%1], %2;\n\t"
            "selp.b32 %0,1,0,p;\n\t}" : "=r"(done) : "r"(mbar), "r"(parity) : "memory");
    }
}
__device__ __forceinline__ void mbar_arrive(uint32_t mbar) {
    asm volatile("mbarrier.arrive.release.cta.shared::cta.b64 _, [%0];" :: "r"(mbar) : "memory");
}
__device__ __forceinline__ void bulk_ld(uint32_t dst, const void* src, uint32_t bytes, uint32_t mb) {
    asm volatile("cp.async.bulk.shared::cluster.global.mbarrier::complete_tx::bytes [%0], [%1], %2, [%3];"
                 :: "r"(dst), "l"(src), "r"(bytes), "r"(mb) : "memory");
}
__device__ __forceinline__ void expect_tx(uint32_t mb, uint32_t bytes) {
    asm volatile("mbarrier.arrive.expect_tx.shared.b64 _, [%0], %1;" :: "r"(mb), "r"(bytes) : "memory");
}
__device__ __forceinline__ void ldsm4(uint32_t* r, uint32_t a) {
    asm volatile("ldmatrix.sync.aligned.m8n8.x4.shared.b16 {%0,%1,%2,%3}, [%4];"
        : "=r"(r[0]), "=r"(r[1]), "=r"(r[2]), "=r"(r[3]) : "r"(a));
}
__device__ __forceinline__ void hmma(float* c, const uint32_t* a, uint32_t b0, uint32_t b1) {
    asm volatile("mma.sync.aligned.m16n8k16.row.col.f32.bf16.bf16.f32 "
        "{%0,%1,%2,%3}, {%4,%5,%6,%7}, {%8,%9}, {%0,%1,%2,%3};"
        : "+f"(c[0]), "+f"(c[1]), "+f"(c[2]), "+f"(c[3])
        : "r"(a[0]), "r"(a[1]), "r"(a[2]), "r"(a[3]), "r"(b0), "r"(b1));
}
__device__ __forceinline__ uint32_t swadr(uint32_t base, int row, int colByte) {
    return base + row * 128 + (colByte ^ ((row & 7) << 4));
}
__device__ __forceinline__ void wr1(bf16* base, int col, int b, bf16 v) {
    base[(size_t)(col >> 6) * ACHK + b * 64 + ((col & 63) ^ ((b & 7) << 3))] = v;
}

// ---------------- cell phase ----------------
__device__ void cell_tc(char* dyn, PS& ps,
    const bf16* Ag, bf16* Agw, const bf16* Wg, int KB, const float* bias, float* cst,
    bf16* h0d, int h0off, bf16* h1d,
    bf16* xdst, const bf16* xsrc, int xt,
    const float* hid, const float* w2, const float* b2p, float* out, int t)
{
    const int tid = threadIdx.x, cta = blockIdx.x;
    const int b0 = (cta >> 4) * 128, u0 = (cta & 15) * 32, w0 = (cta & 15) * 128;
    const int nCh = KB >> 6;
    uint32_t sm0 = (uint32_t)__cvta_generic_to_shared(dyn);

    // decoder cell0: pred(t-1) -> gmem A col0 BEFORE any TMA issue
    if (hid != nullptr) {
        if (t > 0) {
            const int prow = tid >> 2, pq = tid & 3;
            const float* hr = hid + (size_t)(b0 + prow) * 256 + pq * 64;
            const float* wr = w2 + pq * 64;
            float s = 0.f;
            #pragma unroll 8
            for (int j = 0; j < 64; j++) s += __ldcg(hr + j) * __ldg(wr + j);
            s += __shfl_xor_sync(0xffffffffu, s, 1);
            s += __shfl_xor_sync(0xffffffffu, s, 2);
            float myp = fmaxf(s + __ldg(b2p), 0.f);
            if (pq == 0) {
                if ((cta & 15) == 0) out[(size_t)(b0 + prow) * TOUT + (t - 1)] = myp;
                wr1(Agw, 0, b0 + prow, __float2bfloat16(myp));
            }
            __threadfence();
        }
        __syncthreads();
    }

    auto prod = [&](int kc) {
        if (tid == 0) {
            unsigned st = ps.nIss % NST;
            if (ps.nIss >= NST) {
                mbar_wait(sm0 + 64 + st * 8, (ps.pe >> st) & 1);
                ps.pe ^= 1u << st;
            }
            uint32_t mb = sm0 + st * 8;
            expect_tx(mb, 32768u);
            uint32_t d = sm0 + 1024 + st * STG_B;
            bulk_ld(d,         Ag + (size_t)kc * ACHK + b0 * 64, 16384u, mb);
            bulk_ld(d + 16384, Wg + (size_t)kc * WCHK + w0 * 64, 16384u, mb);
        }
        ps.nIss++;
    };
    #pragma unroll
    for (int k = 0; k < NST; k++) prod(k);

    const int lane = tid & 31, warp = tid >> 5;
    const int mi = warp >> 2, nj = warp & 3;
    const int la = lane & 15, lb = (lane >> 4) << 4;
    float acc[2][4][4];
    #pragma unroll
    for (int i = 0; i < 2; i++)
        #pragma unroll
        for (int j = 0; j < 4; j++)
            #pragma unroll
            for (int k = 0; k < 4; k++) acc[i][j][k] = 0.f;

    for (int kc = 0; kc < nCh; kc++) {
        unsigned st = ps.nCon % NST;
        mbar_wait(sm0 + st * 8, (ps.pf >> st) & 1);
        ps.pf ^= 1u << st;
        uint32_t Ab = sm0 + 1024 + st * STG_B, Bb = Ab + 16384;
        #pragma unroll
        for (int k16 = 0; k16 < 4; k16++) {
            int cb = lb + k16 * 32;
            uint32_t a0[4], a1[4], q[4];
            ldsm4(a0, swadr(Ab, mi * 32 + la, cb));
            ldsm4(a1, swadr(Ab, mi * 32 + 16 + la, cb));
            ldsm4(q, swadr(Bb, nj * 32 + la, cb));
            hmma(acc[0][0], a0, q[0], q[2]); hmma(acc[0][1], a0, q[1], q[3]);
            hmma(acc[1][0], a1, q[0], q[2]); hmma(acc[1][1], a1, q[1], q[3]);
            ldsm4(q, swadr(Bb, nj * 32 + 16 + la, cb));
            hmma(acc[0][2], a0, q[0], q[2]); hmma(acc[0][3], a0, q[1], q[3]);
            hmma(acc[1][2], a1, q[0], q[2]); hmma(acc[1][3], a1, q[1], q[3]);
        }
        if (lane == 0) mbar_arrive(sm0 + 64 + st * 8);
        ps.nCon++;
        if (NST + kc < nCh) prod(NST + kc);
    }

    const int qq = lane & 3, r = lane >> 2;
    #pragma unroll
    for (int im = 0; im < 2; im++)
        #pragma unroll
        for (int jn = 0; jn < 4; jn++) {
            float* c4 = acc[im][jn];
            float x0 = __shfl_xor_sync(0xffffffffu, c4[0], 1);
            float x1 = __shfl_xor_sync(0xffffffffu, c4[1], 1);
            float x2 = __shfl_xor_sync(0xffffffffu, c4[2], 1);
            float x3 = __shfl_xor_sync(0xffffffffu, c4[3], 1);
            int u = u0 + nj * 8 + jn * 2 + (qq >> 1);
            int row; float gi, gf, gg, go;
            if ((qq & 1) == 0) { row = mi * 32 + im * 16 + r;     gi = c4[0]; gf = c4[1]; gg = x0;    go = x1; }
            else               { row = mi * 32 + im * 16 + r + 8; gi = x2;    gf = x3;    gg = c4[2]; go = c4[3]; }
            int b = b0 + row;
            gi += __ldg(bias + u);
            gf += __ldg(bias + 512 + u);
            gg += __ldg(bias + 1024 + u);
            go += __ldg(bias + 1536 + u);
            float co = cst[(size_t)u * Bv + b];
            float cn = sigf(gf) * co + sigf(gi) * tanhf(gg);
            float h  = sigf(go) * tanhf(cn);
            cst[(size_t)u * Bv + b] = cn;
            bf16 hb = __float2bfloat16(h);
            wr1(h0d, h0off + u, b, hb);
            if (h1d) wr1(h1d, u, b, hb);
        }

    if (xdst && (cta & 15) == 0) {
        for (int i = tid; i < 256; i += NTHR) {
            int row = i >> 1, seg = i & 1;
            int b = b0 + row;
            uint4* d = (uint4*)(xdst + (size_t)b * 64 + ((seg * 8) ^ ((b & 7) << 3)));
            if (xsrc) *d = *(const uint4*)(xsrc + ((size_t)b * TIN + xt) * 16 + seg * 8);
            else      *d = make_uint4(0, 0, 0, 0);
        }
    }
}

// ---------------- fc1 ----------------
__device__ void fc_phase(char* dyn, PS& ps, const float* fb1, const bf16* A1rd)
{
    const int tid = threadIdx.x, cta = blockIdx.x;
    const int b0 = (cta >> 3) * 64, n0 = (cta & 7) * 32;
    const int nCh = 8;
    uint32_t sm0 = (uint32_t)__cvta_generic_to_shared(dyn);

    auto prod = [&](int kc) {
        if (tid == 0) {
            unsigned st = ps.nIss % NST;
            if (ps.nIss >= NST) {
                mbar_wait(sm0 + 64 + st * 8, (ps.pe >> st) & 1);
                ps.pe ^= 1u << st;
            }
            uint32_t mb = sm0 + st * 8;
            expect_tx(mb, 12288u);
            uint32_t d = sm0 + 1024 + st * STG_B;
            bulk_ld(d,        A1rd + (size_t)(8 + kc) * ACHK + b0 * 64, 8192u, mb);
            bulk_ld(d + 8192, g_Wf1 + (size_t)kc * FCHK + n0 * 64, 4096u, mb);
        }
        ps.nIss++;
    };
    #pragma unroll
    for (int k = 0; k < NST; k++) prod(k);

    const int lane = tid & 31, warp = tid >> 5;
    const int la = lane & 15, lb = (lane >> 4) << 4;
    const int mi = warp >> 1, nj = warp & 1;
    float acc[2][4];
    #pragma unroll
    for (int j = 0; j < 2; j++)
        #pragma unroll
        for (int k = 0; k < 4; k++) acc[j][k] = 0.f;

    for (int kc = 0; kc < nCh; kc++) {
        unsigned st = ps.nCon % NST;
        mbar_wait(sm0 + st * 8, (ps.pf >> st) & 1);
        ps.pf ^= 1u << st;
        if (warp < 8) {
            uint32_t Ab = sm0 + 1024 + st * STG_B, Bb = Ab + 8192;
            #pragma unroll
            for (int k16 = 0; k16 < 4; k16++) {
                int cb = lb + k16 * 32;
                uint32_t a[4], q[4];
                ldsm4(a, swadr(Ab, mi * 16 + la, cb));
                ldsm4(q, swadr(Bb, nj * 16 + la, cb));
                hmma(acc[0], a, q[0], q[2]);
                hmma(acc[1], a, q[1], q[3]);
            }
        }
        if (lane == 0) mbar_arrive(sm0 + 64 + st * 8);
        ps.nCon++;
        if (NST + kc < nCh) prod(NST + kc);
    }
    if (warp < 8) {
        #pragma unroll
        for (int jb = 0; jb < 2; jb++) {
            int n = n0 + nj * 16 + jb * 8 + (lane & 3) * 2;
            int r0 = b0 + mi * 16 + (lane >> 2);
            g_hid[(size_t)r0 * 256 + n]           = fmaxf(acc[jb][0] + __ldg(fb1 + n), 0.f);
            g_hid[(size_t)r0 * 256 + n + 1]       = fmaxf(acc[jb][1] + __ldg(fb1 + n + 1), 0.f);
            g_hid[(size_t)(r0 + 8) * 256 + n]     = fmaxf(acc[jb][2] + __ldg(fb1 + n), 0.f);
            g_hid[(size_t)(r0 + 8) * 256 + n + 1] = fmaxf(acc[jb][3] + __ldg(fb1 + n + 1), 0.f);
        }
    }
}

extern __shared__ __align__(1024) char dynsm[];
__global__ void __launch_bounds__(NTHR, 1) lstm_main(
    const float* eb0, const float* eb1, const float* db0, const float* db1,
    const float* fb1, const float* fW2, const float* fb2, float* out)
{
    const int tid = threadIdx.x;
    uint32_t sm0 = (uint32_t)__cvta_generic_to_shared(dynsm);
    if (tid == 0) {
        #pragma unroll
        for (int s = 0; s < NST; s++) {
            asm volatile("mbarrier.init.shared.b64 [%0], %1;" :: "r"(sm0 + s * 8), "r"(1u) : "memory");
            asm volatile("mbarrier.init.shared.b64 [%0], %1;" :: "r"(sm0 + 64 + s * 8), "r"(16u) : "memory");
        }
    }
    __syncthreads();
    PS ps; ps.pf = 0; ps.pe = 0; ps.nIss = 0; ps.nCon = 0;
    const size_t A0SZ = (size_t)Bv * KB0, A1SZ = (size_t)Bv * KB1;

    for (int i = 0; i <= TIN; i++) {
        if (i < TIN)
            cell_tc(dynsm, ps, g_A0 + (i & 1) * A0SZ, nullptr, g_We0, KB0, eb0, g_c0,
                    g_A0 + ((i + 1) & 1) * A0SZ, 16, g_A1 + (i & 1) * A1SZ,
                    g_A0 + ((i + 1) & 1) * A0SZ, (i + 1 < TIN) ? g_xb : nullptr, i + 1,
                    nullptr, nullptr, nullptr, nullptr, 0);
        if (i > 0)
            cell_tc(dynsm, ps, g_A1 + ((i + 1) & 1) * A1SZ, nullptr, g_We1, KB1, eb1, g_c1,
                    g_A1 + (i & 1) * A1SZ, 512, nullptr,
                    nullptr, nullptr, 0, nullptr, nullptr, nullptr, nullptr, 0);
        gbar();
    }

    int p = 0, q = 0;
    for (int td = 0; td < TOUT; td++) {
        cell_tc(dynsm, ps, g_A0 + p * A0SZ, g_A0 + p * A0SZ, g_Wd0, KB0, db0, g_c0,
                g_A0 + (p ^ 1) * A0SZ, 16, g_A1 + q * A1SZ,
                g_A0 + (p ^ 1) * A0SZ, nullptr, 0,
                g_hid, fW2, fb2, out, td);
        gbar();
        cell_tc(dynsm, ps, g_A1 + q * A1SZ, nullptr, g_Wd1, KB1, db1, g_c1,
                g_A1 + (q ^ 1) * A1SZ, 512, nullptr,
                nullptr, nullptr, 0, nullptr, nullptr, nullptr, nullptr, 0);
        gbar();
        fc_phase(dynsm, ps, fb1, g_A1 + (q ^ 1) * A1SZ);
        gbar();
        p ^= 1; q ^= 1;
    }

    int gid = blockIdx.x * NTHR + tid;
    if (gid < 4096) {
        int b = gid >> 2, pq4 = gid & 3;
        const float* hr = g_hid + (size_t)b * 256 + pq4 * 64;
        const float* wr = fW2 + pq4 * 64;
        float s = 0.f;
        #pragma unroll 8
        for (int j = 0; j < 64; j++) s += __ldcg(hr + j) * __ldg(wr + j);
        s += __shfl_xor_sync(0xffffffffu, s, 1);
        s += __shfl_xor_sync(0xffffffffu, s, 2);
        if (pq4 == 0) out[(size_t)b * TOUT + 167] = fmaxf(s + __ldg(fb2), 0.f);
    }
}

// ---------------- prep ----------------
__device__ void fill_w(const float* Wih, const float* Whh, bf16* dst,
                       int rows, size_t chk, int Fin, int Fpad, int Kf, int KB, int il)
{
    size_t stride = (size_t)gridDim.x * blockDim.x;
    size_t tot = (size_t)rows * KB;
    for (size_t e = (size_t)blockIdx.x * blockDim.x + threadIdx.x; e < tot; e += stride) {
        int kc = (int)(e / chk);
        int rem = (int)(e - (size_t)kc * chk);
        int rp = rem >> 6, cs = rem & 63;
        int col = kc * 64 + (cs ^ ((rp & 7) << 3));
        int g = il ? ((rp & 3) * 512 + (rp >> 2)) : rp;
        float v = 0.f;
        if (col < Fpad)      v = (col < Fin) ? Wih[(size_t)g * Fin + col] : 0.f;
        else if (col < Kf)   v = Whh[(size_t)g * Hv + (col - Fpad)];
        dst[e] = __float2bfloat16(v);
    }
}

__global__ void prep_all(const float* x,
    const float* eWih0, const float* eWhh0, const float* eWih1, const float* eWhh1,
    const float* dWih0, const float* dWhh0, const float* dWih1, const float* dWhh1,
    const float* fW1)
{
    size_t stride = (size_t)gridDim.x * blockDim.x;
    size_t i0 = (size_t)blockIdx.x * blockDim.x + threadIdx.x;

    for (size_t e = i0; e < (size_t)2 * Bv * KB0; e += stride) {
        size_t pz = e / ((size_t)Bv * KB0);
        size_t i = e - pz * (size_t)Bv * KB0;
        int kc = (int)(i / ACHK);
        int rem = (int)(i - (size_t)kc * ACHK);
        int b = rem >> 6, cs = rem & 63;
        int col = kc * 64 + (cs ^ ((b & 7) << 3));
        float v = 0.f;
        if (pz == 0 && col < 16) v = x[(size_t)b * (TIN * 16) + col];
        g_A0[e] = __float2bfloat16(v);
    }
    for (size_t e = i0; e < (size_t)2 * Bv * KB1; e += stride) g_A1[e] = __float2bfloat16(0.f);
    for (size_t e = i0; e < (size_t)Bv * Hv; e += stride) { g_c0[e] = 0.f; g_c1[e] = 0.f; }
    for (size_t e = i0; e < (size_t)Bv * TIN * 16; e += stride)
        g_xb[e] = __float2bfloat16(x[e]);

    fill_w(eWih0, eWhh0, g_We0, 2048, WCHK, 16, 16, 528, KB0, 1);
    fill_w(eWih1, eWhh1, g_We1, 2048, WCHK, 512, 512, 1024, KB1, 1);
    fill_w(dWih0, dWhh0, g_Wd0, 2048, WCHK, 1, 16, 528, KB0, 1);
    fill_w(dWih1, dWhh1, g_Wd1, 2048, WCHK, 512, 512, 1024, KB1, 1);
    fill_w(fW1, nullptr, g_Wf1, 256, FCHK, 512, 512, 512, KBF, 0);
}

extern "C" void kernel_launch(void* const* d_in, const int* in_sizes, int n_in,
                              void* d_out, int out_size)
{
    const float* x     = (const float*)d_in[0];
    const float* eWih0 = (const float*)d_in[1];
    const float* eWhh0 = (const float*)d_in[2];
    const float* eb0   = (const float*)d_in[3];
    const float* eWih1 = (const float*)d_in[4];
    const float* eWhh1 = (const float*)d_in[5];
    const float* eb1   = (const float*)d_in[6];
    const float* dWih0 = (const float*)d_in[7];
    const float* dWhh0 = (const float*)d_in[8];
    const float* db0   = (const float*)d_in[9];
    const float* dWih1 = (const float*)d_in[10];
    const float* dWhh1 = (const float*)d_in[11];
    const float* db1   = (const float*)d_in[12];
    const float* fW1   = (const float*)d_in[13];
    const float* fb1   = (const float*)d_in[14];
    const float* fW2   = (const float*)d_in[15];
    const float* fb2   = (const float*)d_in[16];
    float* out = (float*)d_out;

    cudaFuncSetAttribute(lstm_main, cudaFuncAttributeMaxDynamicSharedMemorySize, DSM);
    prep_all<<<512, 256>>>(x, eWih0, eWhh0, eWih1, eWhh1, dWih0, dWhh0, dWih1, dWhh1, fW1);
    lstm_main<<<NCTA, NTHR, DSM>>>(eb0, eb1, db0, db1, fb1, fW2, fb2, out);
}